// round 1
// baseline (speedup 1.0000x reference)
#include <cuda_runtime.h>
#include <math.h>

#define N_SRC   65536
#define N_DST   16384
#define NE      262144
#define IN_F    256
#define HIDD    128
#define NH      4
#define FDIM    512      /* NH*HIDD */
#define KNB     50
#define CAP     1024
#define NEG_SLOPE 0.2f

/* ---------------- scratch (static device globals: allocation-free) -------- */
__device__ float  g_feat_src[(size_t)N_SRC * FDIM];   /* 128 MB */
__device__ float  g_res     [(size_t)N_DST * FDIM];   /* 32 MB  */
__device__ float  g_dist    [(size_t)N_DST * HIDD];   /* 8 MB   */
__device__ float  g_el      [N_SRC * NH];
__device__ float  g_er      [N_DST * NH];
__device__ float  g_s       [N_DST];
__device__ int    g_counts  [N_DST];
__device__ int    g_off     [N_DST + 1];
__device__ int    g_cursor  [N_DST];
__device__ int    g_csr_src [NE];
__device__ float4 g_csr_e   [NE];

/* ---------------- utility ------------------------------------------------- */
__global__ void zero_counts_kernel() {
    int i = blockIdx.x * blockDim.x + threadIdx.x;
    if (i < N_DST) g_counts[i] = 0;
}

/* ---------------- SGEMM: C[M,N] = A[M,K] @ B[N,K]^T, K=256 ----------------
   BM=128, BN=64, BK=16, 256 threads, thread tile 8x4.
   which: 0 -> g_feat_src, 1 -> g_res, 2 -> g_dist.
   gather: optional row-index indirection for A. */
__global__ void __launch_bounds__(256)
sgemm_nt(const float* __restrict__ A, const float* __restrict__ B,
         const int* __restrict__ gather, int N, int which)
{
    float* Cbase = (which == 0) ? g_feat_src : (which == 1) ? g_res : g_dist;

    __shared__ float As[16][128];
    __shared__ float Bs[16][64];

    const int tid = threadIdx.x;
    const int m0 = blockIdx.x * 128;
    const int n0 = blockIdx.y * 64;
    const int tm = tid >> 4;          /* 0..15 */
    const int tn = tid & 15;          /* 0..15 */
    const int ar = tid >> 2;          /* 0..63 */
    const int ac = (tid & 3) * 4;     /* 0,4,8,12 */

    int grow0 = m0 + ar;
    int grow1 = m0 + ar + 64;
    if (gather) { grow0 = gather[grow0]; grow1 = gather[grow1]; }
    const float* Arow0 = A + (size_t)grow0 * IN_F;
    const float* Arow1 = A + (size_t)grow1 * IN_F;
    const float* Brow  = B + (size_t)(n0 + ar) * IN_F;

    float acc[8][4];
#pragma unroll
    for (int i = 0; i < 8; i++)
#pragma unroll
        for (int j = 0; j < 4; j++) acc[i][j] = 0.f;

    for (int k0 = 0; k0 < IN_F; k0 += 16) {
        float4 va0 = *(const float4*)(Arow0 + k0 + ac);
        float4 va1 = *(const float4*)(Arow1 + k0 + ac);
        float4 vb  = *(const float4*)(Brow  + k0 + ac);

        As[ac + 0][ar]      = va0.x; As[ac + 1][ar]      = va0.y;
        As[ac + 2][ar]      = va0.z; As[ac + 3][ar]      = va0.w;
        As[ac + 0][ar + 64] = va1.x; As[ac + 1][ar + 64] = va1.y;
        As[ac + 2][ar + 64] = va1.z; As[ac + 3][ar + 64] = va1.w;
        Bs[ac + 0][ar] = vb.x; Bs[ac + 1][ar] = vb.y;
        Bs[ac + 2][ar] = vb.z; Bs[ac + 3][ar] = vb.w;
        __syncthreads();

#pragma unroll
        for (int kk = 0; kk < 16; kk++) {
            float4 a0 = *(const float4*)&As[kk][tm * 8];
            float4 a1 = *(const float4*)&As[kk][tm * 8 + 4];
            float4 b  = *(const float4*)&Bs[kk][tn * 4];
            float av[8] = {a0.x, a0.y, a0.z, a0.w, a1.x, a1.y, a1.z, a1.w};
            float bv[4] = {b.x, b.y, b.z, b.w};
#pragma unroll
            for (int i = 0; i < 8; i++)
#pragma unroll
                for (int j = 0; j < 4; j++)
                    acc[i][j] = fmaf(av[i], bv[j], acc[i][j]);
        }
        __syncthreads();
    }

#pragma unroll
    for (int i = 0; i < 8; i++) {
        float4 v = make_float4(acc[i][0], acc[i][1], acc[i][2], acc[i][3]);
        *(float4*)&Cbase[(size_t)(m0 + tm * 8 + i) * N + n0 + tn * 4] = v;
    }
}

/* ---------------- el / er: per-node per-head dot with attn vectors -------- */
__global__ void __launch_bounds__(256)
el_er_kernel(const float* __restrict__ attn_l, const float* __restrict__ attn_r)
{
    __shared__ float sal[FDIM];
    __shared__ float sar[FDIM];
    const int tid = threadIdx.x;
    for (int i = tid; i < FDIM; i += 256) { sal[i] = attn_l[i]; sar[i] = attn_r[i]; }
    __syncthreads();

    const int lane = tid & 31, warp = tid >> 5;
    const int n = blockIdx.x * 8 + warp;
    const float* row = g_feat_src + (size_t)n * FDIM;
    const bool isdst = (n < N_DST);

#pragma unroll
    for (int h = 0; h < NH; h++) {
        float pl = 0.f, pr = 0.f;
#pragma unroll
        for (int i = 0; i < 4; i++) {
            int d = h * HIDD + lane + i * 32;
            float v = row[d];
            pl = fmaf(v, sal[d], pl);
            pr = fmaf(v, sar[d], pr);
        }
#pragma unroll
        for (int o = 16; o; o >>= 1) {
            pl += __shfl_xor_sync(0xffffffffu, pl, o);
            pr += __shfl_xor_sync(0xffffffffu, pr, o);
        }
        if (lane == 0) {
            g_el[n * NH + h] = pl;
            if (isdst) g_er[n * NH + h] = pr;
        }
    }
}

/* ---------------- histogram / scan / scatter (CSR build) ------------------ */
__global__ void hist_kernel(const int* __restrict__ dst_idx)
{
    int e = blockIdx.x * blockDim.x + threadIdx.x;
    if (e < NE) atomicAdd(&g_counts[dst_idx[e]], 1);
}

__global__ void __launch_bounds__(1024) scan_kernel()
{
    __shared__ int tmp[1024];
    const int tid = threadIdx.x;
    const int base = tid * 16;
    int loc[16];
    int s = 0;
#pragma unroll
    for (int j = 0; j < 16; j++) { loc[j] = s; s += g_counts[base + j]; }
    tmp[tid] = s;
    __syncthreads();
    for (int o = 1; o < 1024; o <<= 1) {
        int v = (tid >= o) ? tmp[tid - o] : 0;
        __syncthreads();
        tmp[tid] += v;
        __syncthreads();
    }
    int excl = tmp[tid] - s;
#pragma unroll
    for (int j = 0; j < 16; j++) {
        int v = excl + loc[j];
        g_off[base + j] = v;
        g_cursor[base + j] = v;
    }
    if (tid == 1023) g_off[N_DST] = excl + s;
}

__global__ void scatter_kernel(const int* __restrict__ src_idx,
                               const int* __restrict__ dst_idx)
{
    int e = blockIdx.x * blockDim.x + threadIdx.x;
    if (e >= NE) return;
    int s = src_idx[e];
    int d = dst_idx[e];
    const float* el = g_el + s * NH;
    const float* er = g_er + d * NH;
    float4 ev;
    float x;
    x = el[0] + er[0]; ev.x = (x > 0.f) ? x : NEG_SLOPE * x;
    x = el[1] + er[1]; ev.y = (x > 0.f) ? x : NEG_SLOPE * x;
    x = el[2] + er[2]; ev.z = (x > 0.f) ? x : NEG_SLOPE * x;
    x = el[3] + er[3]; ev.w = (x > 0.f) ? x : NEG_SLOPE * x;
    int pos = atomicAdd(&g_cursor[d], 1);
    g_csr_src[pos] = s;
    g_csr_e[pos]   = ev;
}

/* ---------------- s[d] = sum of first min(count,K) poi_coeff -------------- */
__global__ void __launch_bounds__(256)
s_kernel(const float* __restrict__ poi_coeff, const int* __restrict__ output_nodes,
         const int* __restrict__ ncounts)
{
    const int lane = threadIdx.x & 31, warp = threadIdx.x >> 5;
    const int d = blockIdx.x * 8 + warp;
    if (d >= N_DST) return;
    int node = output_nodes[d];
    int c = ncounts[node];
    if (c > KNB) c = KNB;
    float p = 0.f;
    for (int j = lane; j < c; j += 32) p += poi_coeff[(size_t)node * KNB + j];
#pragma unroll
    for (int o = 16; o; o >>= 1) p += __shfl_xor_sync(0xffffffffu, p, o);
    if (lane == 0) g_s[d] = p;
}

/* ---------------- per-dst softmax + aggregation + fused epilogue ---------- */
__global__ void __launch_bounds__(128)
aggregate_kernel(const float* __restrict__ bias, float* __restrict__ out)
{
    const int d    = blockIdx.x;
    const int tid  = threadIdx.x;           /* 128: tid = dd */
    const int lane = tid & 31, warp = tid >> 5;
    const int beg  = g_off[d];
    const int deg  = g_off[d + 1] - beg;

    __shared__ float sa[CAP * 4];
    __shared__ int   ssrc[CAP];
    __shared__ float red[4][4];
    __shared__ float smx[4], sinv[4];

    /* ---- pass 1: per-head max ---- */
    float m0 = -3e38f, m1 = -3e38f, m2 = -3e38f, m3 = -3e38f;
    for (int e = tid; e < deg; e += 128) {
        float4 v = g_csr_e[beg + e];
        m0 = fmaxf(m0, v.x); m1 = fmaxf(m1, v.y);
        m2 = fmaxf(m2, v.z); m3 = fmaxf(m3, v.w);
    }
#pragma unroll
    for (int o = 16; o; o >>= 1) {
        m0 = fmaxf(m0, __shfl_xor_sync(0xffffffffu, m0, o));
        m1 = fmaxf(m1, __shfl_xor_sync(0xffffffffu, m1, o));
        m2 = fmaxf(m2, __shfl_xor_sync(0xffffffffu, m2, o));
        m3 = fmaxf(m3, __shfl_xor_sync(0xffffffffu, m3, o));
    }
    if (lane == 0) { red[warp][0] = m0; red[warp][1] = m1; red[warp][2] = m2; red[warp][3] = m3; }
    __syncthreads();
    if (tid < 4)
        smx[tid] = fmaxf(fmaxf(red[0][tid], red[1][tid]), fmaxf(red[2][tid], red[3][tid]));
    __syncthreads();
    m0 = smx[0]; m1 = smx[1]; m2 = smx[2]; m3 = smx[3];

    /* ---- pass 2: exp + denom, stash weights in shared (deg <= CAP) ---- */
    float d0 = 0.f, d1 = 0.f, d2 = 0.f, d3 = 0.f;
    for (int e = tid; e < deg; e += 128) {
        float4 v = g_csr_e[beg + e];
        float w0 = __expf(v.x - m0), w1 = __expf(v.y - m1);
        float w2 = __expf(v.z - m2), w3 = __expf(v.w - m3);
        if (e < CAP) {
            sa[e * 4 + 0] = w0; sa[e * 4 + 1] = w1;
            sa[e * 4 + 2] = w2; sa[e * 4 + 3] = w3;
            ssrc[e] = g_csr_src[beg + e];
        }
        d0 += w0; d1 += w1; d2 += w2; d3 += w3;
    }
#pragma unroll
    for (int o = 16; o; o >>= 1) {
        d0 += __shfl_xor_sync(0xffffffffu, d0, o);
        d1 += __shfl_xor_sync(0xffffffffu, d1, o);
        d2 += __shfl_xor_sync(0xffffffffu, d2, o);
        d3 += __shfl_xor_sync(0xffffffffu, d3, o);
    }
    if (lane == 0) { red[warp][0] = d0; red[warp][1] = d1; red[warp][2] = d2; red[warp][3] = d3; }
    __syncthreads();
    if (tid < 4) {
        float den = red[0][tid] + red[1][tid] + red[2][tid] + red[3][tid];
        sinv[tid] = 1.0f / fmaxf(den, 1e-9f);
    }
    __syncthreads();

    /* ---- pass 3: weighted aggregation (unnormalized, scale at end) ---- */
    float a0 = 0.f, a1 = 0.f, a2 = 0.f, a3 = 0.f;
    for (int e = 0; e < deg; e++) {
        int s;
        float w0, w1, w2, w3;
        if (e < CAP) {
            s = ssrc[e];
            w0 = sa[e * 4 + 0]; w1 = sa[e * 4 + 1];
            w2 = sa[e * 4 + 2]; w3 = sa[e * 4 + 3];
        } else {
            s = g_csr_src[beg + e];
            float4 v = g_csr_e[beg + e];
            w0 = __expf(v.x - m0); w1 = __expf(v.y - m1);
            w2 = __expf(v.z - m2); w3 = __expf(v.w - m3);
        }
        const float* fs = g_feat_src + (size_t)s * FDIM + tid;
        a0 = fmaf(w0, fs[0],   a0);
        a1 = fmaf(w1, fs[128], a1);
        a2 = fmaf(w2, fs[256], a2);
        a3 = fmaf(w3, fs[384], a3);
    }

    /* ---- epilogue: elu(rst + res + bias), +dist*s, /2, relu ---- */
    const float sd   = g_s[d];
    const float dist = g_dist[(size_t)d * HIDD + tid] * sd;
    const size_t ob  = (size_t)d * FDIM + tid;
    float accs[4] = {a0 * sinv[0], a1 * sinv[1], a2 * sinv[2], a3 * sinv[3]};
#pragma unroll
    for (int h = 0; h < 4; h++) {
        float x = accs[h] + g_res[ob + h * 128] + bias[h * 128 + tid];
        float eluv = (x > 0.f) ? x : expm1f(x);
        float o = (eluv + dist) * 0.5f;
        out[ob + h * 128] = (o > 0.f) ? o : 0.f;
    }
}

/* ---------------- launch -------------------------------------------------- */
extern "C" void kernel_launch(void* const* d_in, const int* in_sizes, int n_in,
                              void* d_out, int out_size)
{
    const float* feat       = (const float*)d_in[0];
    const float* poi_cat    = (const float*)d_in[1];
    const float* poi_coeff  = (const float*)d_in[2];
    const float* fc_w       = (const float*)d_in[3];
    const float* attn_l     = (const float*)d_in[4];
    const float* attn_r     = (const float*)d_in[5];
    const float* bias_p     = (const float*)d_in[6];
    const float* res_w      = (const float*)d_in[7];
    const float* w_w        = (const float*)d_in[8];
    const int*   src_idx    = (const int*)d_in[9];
    const int*   dst_idx    = (const int*)d_in[10];
    const int*   out_nodes  = (const int*)d_in[11];
    const int*   ncounts    = (const int*)d_in[12];
    float*       out        = (float*)d_out;

    zero_counts_kernel<<<N_DST / 256, 256>>>();

    /* GEMM1: feat_src = feat @ fc_w^T  [65536 x 512] */
    sgemm_nt<<<dim3(N_SRC / 128, FDIM / 64), 256>>>(feat, fc_w, nullptr, FDIM, 0);
    /* GEMM2: res = feat[:Ndst] @ res_w^T  [16384 x 512] */
    sgemm_nt<<<dim3(N_DST / 128, FDIM / 64), 256>>>(feat, res_w, nullptr, FDIM, 1);
    /* GEMM3: dist = poi_cat[gather] @ w_w^T  [16384 x 128] */
    sgemm_nt<<<dim3(N_DST / 128, HIDD / 64), 256>>>(poi_cat, w_w, out_nodes, HIDD, 2);

    el_er_kernel<<<N_SRC / 8, 256>>>(attn_l, attn_r);
    hist_kernel<<<NE / 256, 256>>>(dst_idx);
    scan_kernel<<<1, 1024>>>();
    scatter_kernel<<<NE / 256, 256>>>(src_idx, dst_idx);
    s_kernel<<<N_DST / 8, 256>>>(poi_coeff, out_nodes, ncounts);
    aggregate_kernel<<<N_DST, 128>>>(bias_p, out);
}

// round 3
// speedup vs baseline: 1.4133x; 1.4133x over previous
#include <cuda_runtime.h>
#include <cuda_bf16.h>
#include <math.h>
#include <stdint.h>

#define N_SRC   65536
#define N_DST   16384
#define NE      262144
#define IN_F    256
#define HIDD    128
#define NH      4
#define FDIM    512      /* NH*HIDD */
#define KNB     50
#define CAP     1024
#define NEG_SLOPE 0.2f

/* smem tile layout for the mma GEMM (byte offsets). Row stride 72 bf16 =
   144 B so 8 consecutive rows land in 8 distinct 16B chunks (mod 128) ->
   ldmatrix conflict-free. */
#define ASTRIDE_E 72        /* bf16 elems per row (64 used + 8 pad) */
#define ASTRIDE_B 144       /* bytes per row */
#define TILE_B    (128 * ASTRIDE_B)   /* 18432 */
#define SM_AHI    0
#define SM_ALO    (SM_AHI + TILE_B)
#define SM_BHI    (SM_ALO + TILE_B)
#define SM_BLO    (SM_BHI + TILE_B)
#define SM_ELS    (SM_BLO + TILE_B)   /* 73728: float[128] el partial */
#define SM_ERS    (SM_ELS + 512)
#define SM_TOTAL  (SM_ERS + 512)      /* 74752 */

/* ================= scratch globals ======================================== */
__device__ float  g_feat_src[(size_t)N_SRC * FDIM];
__device__ float  g_res     [(size_t)N_DST * FDIM];
__device__ float  g_dist    [(size_t)N_DST * HIDD];
__device__ float  g_el      [N_SRC * NH];
__device__ float  g_er      [N_DST * NH];
__device__ float  g_s       [N_DST];
__device__ int    g_counts  [N_DST];
__device__ int    g_off     [N_DST + 1];
__device__ int    g_cursor  [N_DST];
__device__ int    g_csr_src [NE];
__device__ float4 g_csr_e   [NE];
/* pre-converted bf16 weight images laid out as [chunk(4)][n(512)][72 bf16] */
__device__ __align__(16) __nv_bfloat16 g_w1hi[4 * 512 * ASTRIDE_E];
__device__ __align__(16) __nv_bfloat16 g_w1lo[4 * 512 * ASTRIDE_E];
__device__ __align__(16) __nv_bfloat16 g_w2hi[4 * 512 * ASTRIDE_E];
__device__ __align__(16) __nv_bfloat16 g_w2lo[4 * 512 * ASTRIDE_E];

/* ================= small PTX wrappers (arch-generic, sm_80+) ============== */
__device__ __forceinline__ uint32_t smem_u32(const void* p) {
    uint32_t a;
    asm("{ .reg .u64 t; cvta.to.shared.u64 t, %1; cvt.u32.u64 %0, t; }"
        : "=r"(a) : "l"(p));
    return a;
}
__device__ __forceinline__ void ldsm4(uint32_t* r, uint32_t addr) {
    asm volatile("ldmatrix.sync.aligned.m8n8.x4.shared.b16 {%0,%1,%2,%3}, [%4];"
                 : "=r"(r[0]), "=r"(r[1]), "=r"(r[2]), "=r"(r[3]) : "r"(addr));
}
__device__ __forceinline__ void ldsm2(uint32_t* r, uint32_t addr) {
    asm volatile("ldmatrix.sync.aligned.m8n8.x2.shared.b16 {%0,%1}, [%2];"
                 : "=r"(r[0]), "=r"(r[1]) : "r"(addr));
}
__device__ __forceinline__ void mma16816(float* c, const uint32_t* a, const uint32_t* b) {
    asm volatile("mma.sync.aligned.m16n8k16.row.col.f32.bf16.bf16.f32 "
                 "{%0,%1,%2,%3}, {%4,%5,%6,%7}, {%8,%9}, {%0,%1,%2,%3};"
                 : "+f"(c[0]), "+f"(c[1]), "+f"(c[2]), "+f"(c[3])
                 : "r"(a[0]), "r"(a[1]), "r"(a[2]), "r"(a[3]),
                   "r"(b[0]), "r"(b[1]));
}

/* ================= weight conversion: fp32 -> bf16 hi/lo images =========== */
__global__ void conv_w_kernel(const float* __restrict__ W, int which)
{
    __nv_bfloat16* dhi = which ? g_w2hi : g_w1hi;
    __nv_bfloat16* dlo = which ? g_w2lo : g_w1lo;
    int p = blockIdx.x * blockDim.x + threadIdx.x;   /* 65536 = 512 n x 128 kpairs */
    int n  = p >> 7;
    int kp = p & 127;
    int col = kp * 2;
    int chunk = col >> 6;
    int klocal = col & 63;
    float x0 = W[n * IN_F + col];
    float x1 = W[n * IN_F + col + 1];
    __nv_bfloat16 h0 = __float2bfloat16(x0);
    __nv_bfloat16 h1 = __float2bfloat16(x1);
    __nv_bfloat16 l0 = __float2bfloat16(x0 - __bfloat162float(h0));
    __nv_bfloat16 l1 = __float2bfloat16(x1 - __bfloat162float(h1));
    size_t off = (size_t)(chunk * 512 + n) * ASTRIDE_E + klocal;
    *(__nv_bfloat162*)(dhi + off) = __nv_bfloat162(h0, h1);
    *(__nv_bfloat162*)(dlo + off) = __nv_bfloat162(l0, l1);
}

/* ================= HMMA GEMM: out[M,512] = A[M,256] @ W[512,256]^T ========
   bf16 hi/lo 3-pass split-precision. grid = (4 heads, M/128).
   which==0: out=g_feat_src, fused el/er epilogue. which==1: out=g_res.     */
__global__ void __launch_bounds__(256, 1)
tc_gemm(const float* __restrict__ A, int which,
        const float* __restrict__ attn_l, const float* __restrict__ attn_r)
{
    extern __shared__ unsigned char smem[];
    const uint32_t sb = smem_u32(smem);
    const int tid  = threadIdx.x;
    const int wid  = tid >> 5;
    const int lane = tid & 31;
    const int wm   = wid & 1;        /* warp row: 2 x 64 rows  */
    const int wn   = wid >> 1;       /* warp col: 4 x 32 cols  */
    const int head = blockIdx.x;     /* 0..3  (128-col slab = one head) */
    const int row0 = blockIdx.y * 128;

    float* out = which ? g_res : g_feat_src;
    const __nv_bfloat16* whi = which ? g_w2hi : g_w1hi;
    const __nv_bfloat16* wlo = which ? g_w2lo : g_w1lo;

    float* els = (float*)(smem + SM_ELS);
    float* ers = (float*)(smem + SM_ERS);
    if (which == 0 && tid < 128) { els[tid] = 0.f; ers[tid] = 0.f; }

    float c[4][4][4];
#pragma unroll
    for (int mt = 0; mt < 4; mt++)
#pragma unroll
        for (int nt = 0; nt < 4; nt++)
#pragma unroll
            for (int j = 0; j < 4; j++) c[mt][nt][j] = 0.f;

    /* per-thread ldmatrix base addresses */
    const uint32_t a_base = sb + SM_AHI + (uint32_t)(wm * 64 + (lane & 15)) * ASTRIDE_B
                            + (uint32_t)(lane >> 4) * 16;
    const uint32_t b_base = sb + SM_BHI + (uint32_t)(wn * 32 + (lane & 7)) * ASTRIDE_B
                            + (uint32_t)((lane >> 3) & 1) * 16;

    const int lr  = tid >> 1;        /* A-load row 0..127 */
    const int seg = tid & 1;         /* A-load col half   */
    const int bn  = tid >> 1;        /* B-copy row 0..127 */
    const int bh  = tid & 1;         /* B-copy 64B half   */

    for (int chunk = 0; chunk < 4; chunk++) {
        const int k0 = chunk * 64;

        /* ---- A: load fp32, split into bf16 hi/lo, store padded rows ---- */
        const float* arow = A + (size_t)(row0 + lr) * IN_F + k0 + seg * 32;
        unsigned char* sa = smem + (size_t)lr * ASTRIDE_B + (seg * 32) * 2;
#pragma unroll
        for (int i = 0; i < 8; i++) {
            float4 v = *(const float4*)(arow + i * 4);
            __nv_bfloat162 h01 = __floats2bfloat162_rn(v.x, v.y);
            __nv_bfloat162 h23 = __floats2bfloat162_rn(v.z, v.w);
            float2 f01 = __bfloat1622float2(h01);
            float2 f23 = __bfloat1622float2(h23);
            __nv_bfloat162 l01 = __floats2bfloat162_rn(v.x - f01.x, v.y - f01.y);
            __nv_bfloat162 l23 = __floats2bfloat162_rn(v.z - f23.x, v.w - f23.y);
            uint2 uh, ul;
            uh.x = *(uint32_t*)&h01; uh.y = *(uint32_t*)&h23;
            ul.x = *(uint32_t*)&l01; ul.y = *(uint32_t*)&l23;
            *(uint2*)(sa + SM_AHI + i * 8) = uh;
            *(uint2*)(sa + SM_ALO + i * 8) = ul;
        }

        /* ---- B: copy pre-converted rows (64 bf16 = 128B used per row) -- */
        {
            size_t grow = (size_t)(chunk * 512 + head * 128 + bn) * ASTRIDE_E;
            const uint4* shb = (const uint4*)(whi + grow) + bh * 4;
            const uint4* slb = (const uint4*)(wlo + grow) + bh * 4;
            uint4* dhb = (uint4*)(smem + SM_BHI + (size_t)bn * ASTRIDE_B + bh * 64);
            uint4* dlb = (uint4*)(smem + SM_BLO + (size_t)bn * ASTRIDE_B + bh * 64);
#pragma unroll
            for (int i = 0; i < 4; i++) { dhb[i] = shb[i]; dlb[i] = slb[i]; }
        }
        __syncthreads();

        /* ---- mma mainloop over 4 k-steps of 16 ---- */
#pragma unroll
        for (int kk = 0; kk < 4; kk++) {
            uint32_t ah[4][4], alo[4][4], bhf[4][2], blf[4][2];
#pragma unroll
            for (int mt = 0; mt < 4; mt++) {
                uint32_t ad = a_base + mt * 16 * ASTRIDE_B + kk * 32;
                ldsm4(ah[mt],  ad);
                ldsm4(alo[mt], ad + (SM_ALO - SM_AHI));
            }
#pragma unroll
            for (int nt = 0; nt < 4; nt++) {
                uint32_t bd = b_base + nt * 8 * ASTRIDE_B + kk * 32;
                ldsm2(bhf[nt], bd);
                ldsm2(blf[nt], bd + (SM_BLO - SM_BHI));
            }
#pragma unroll
            for (int mt = 0; mt < 4; mt++)
#pragma unroll
                for (int nt = 0; nt < 4; nt++) {
                    mma16816(c[mt][nt], ah[mt],  bhf[nt]);
                    mma16816(c[mt][nt], ah[mt],  blf[nt]);
                    mma16816(c[mt][nt], alo[mt], bhf[nt]);
                }
        }
        __syncthreads();
    }

    /* ---- epilogue: store C; fused el/er for which==0 ---- */
    float2 al[4], ar[4];
    if (which == 0) {
#pragma unroll
        for (int nt = 0; nt < 4; nt++) {
            int cg = head * 128 + wn * 32 + nt * 8 + (lane & 3) * 2;
            al[nt] = *(const float2*)(attn_l + cg);
            ar[nt] = *(const float2*)(attn_r + cg);
        }
    }
#pragma unroll
    for (int mt = 0; mt < 4; mt++) {
        int r0 = wm * 64 + mt * 16 + (lane >> 2);
        int r1 = r0 + 8;
        float pl0 = 0.f, pl1 = 0.f, pr0 = 0.f, pr1 = 0.f;
#pragma unroll
        for (int nt = 0; nt < 4; nt++) {
            int cl = wn * 32 + nt * 8 + (lane & 3) * 2;
            float2 v0 = make_float2(c[mt][nt][0], c[mt][nt][1]);
            float2 v1 = make_float2(c[mt][nt][2], c[mt][nt][3]);
            *(float2*)(out + (size_t)(row0 + r0) * FDIM + head * 128 + cl) = v0;
            *(float2*)(out + (size_t)(row0 + r1) * FDIM + head * 128 + cl) = v1;
            if (which == 0) {
                pl0 = fmaf(v0.x, al[nt].x, fmaf(v0.y, al[nt].y, pl0));
                pl1 = fmaf(v1.x, al[nt].x, fmaf(v1.y, al[nt].y, pl1));
                pr0 = fmaf(v0.x, ar[nt].x, fmaf(v0.y, ar[nt].y, pr0));
                pr1 = fmaf(v1.x, ar[nt].x, fmaf(v1.y, ar[nt].y, pr1));
            }
        }
        if (which == 0) {
#pragma unroll
            for (int o = 1; o <= 2; o <<= 1) {
                pl0 += __shfl_xor_sync(0xffffffffu, pl0, o);
                pl1 += __shfl_xor_sync(0xffffffffu, pl1, o);
                pr0 += __shfl_xor_sync(0xffffffffu, pr0, o);
                pr1 += __shfl_xor_sync(0xffffffffu, pr1, o);
            }
            if ((lane & 3) == 0) {
                atomicAdd(&els[r0], pl0); atomicAdd(&els[r1], pl1);
                atomicAdd(&ers[r0], pr0); atomicAdd(&ers[r1], pr1);
            }
        }
    }
    if (which == 0) {
        __syncthreads();
        if (tid < 128) {
            int grow = row0 + tid;
            g_el[grow * NH + head] = els[tid];
            if (grow < N_DST) g_er[grow * NH + head] = ers[tid];
        }
    }
}

/* ================= SIMT GEMM (gathered GEMM3, unchanged from R1) ========== */
__global__ void __launch_bounds__(256)
sgemm_nt(const float* __restrict__ A, const float* __restrict__ B,
         const int* __restrict__ gather, int N)
{
    float* Cbase = g_dist;
    __shared__ float As[16][128];
    __shared__ float Bs[16][64];
    const int tid = threadIdx.x;
    const int m0 = blockIdx.x * 128;
    const int n0 = blockIdx.y * 64;
    const int tm = tid >> 4, tn = tid & 15;
    const int ar = tid >> 2, ac = (tid & 3) * 4;

    int grow0 = m0 + ar, grow1 = m0 + ar + 64;
    if (gather) { grow0 = gather[grow0]; grow1 = gather[grow1]; }
    const float* Arow0 = A + (size_t)grow0 * IN_F;
    const float* Arow1 = A + (size_t)grow1 * IN_F;
    const float* Brow  = B + (size_t)(n0 + ar) * IN_F;

    float acc[8][4];
#pragma unroll
    for (int i = 0; i < 8; i++)
#pragma unroll
        for (int j = 0; j < 4; j++) acc[i][j] = 0.f;

    for (int k0 = 0; k0 < IN_F; k0 += 16) {
        float4 va0 = *(const float4*)(Arow0 + k0 + ac);
        float4 va1 = *(const float4*)(Arow1 + k0 + ac);
        float4 vb  = *(const float4*)(Brow  + k0 + ac);
        As[ac + 0][ar]      = va0.x; As[ac + 1][ar]      = va0.y;
        As[ac + 2][ar]      = va0.z; As[ac + 3][ar]      = va0.w;
        As[ac + 0][ar + 64] = va1.x; As[ac + 1][ar + 64] = va1.y;
        As[ac + 2][ar + 64] = va1.z; As[ac + 3][ar + 64] = va1.w;
        Bs[ac + 0][ar] = vb.x; Bs[ac + 1][ar] = vb.y;
        Bs[ac + 2][ar] = vb.z; Bs[ac + 3][ar] = vb.w;
        __syncthreads();
#pragma unroll
        for (int kk = 0; kk < 16; kk++) {
            float4 a0 = *(const float4*)&As[kk][tm * 8];
            float4 a1 = *(const float4*)&As[kk][tm * 8 + 4];
            float4 b  = *(const float4*)&Bs[kk][tn * 4];
            float av[8] = {a0.x, a0.y, a0.z, a0.w, a1.x, a1.y, a1.z, a1.w};
            float bv[4] = {b.x, b.y, b.z, b.w};
#pragma unroll
            for (int i = 0; i < 8; i++)
#pragma unroll
                for (int j = 0; j < 4; j++)
                    acc[i][j] = fmaf(av[i], bv[j], acc[i][j]);
        }
        __syncthreads();
    }
#pragma unroll
    for (int i = 0; i < 8; i++) {
        float4 v = make_float4(acc[i][0], acc[i][1], acc[i][2], acc[i][3]);
        *(float4*)&Cbase[(size_t)(m0 + tm * 8 + i) * N + n0 + tn * 4] = v;
    }
}

/* ================= CSR build + softmax aggregation (unchanged) ============ */
__global__ void zero_counts_kernel() {
    int i = blockIdx.x * blockDim.x + threadIdx.x;
    if (i < N_DST) g_counts[i] = 0;
}

__global__ void hist_kernel(const int* __restrict__ dst_idx)
{
    int e = blockIdx.x * blockDim.x + threadIdx.x;
    if (e < NE) atomicAdd(&g_counts[dst_idx[e]], 1);
}

__global__ void __launch_bounds__(1024) scan_kernel()
{
    __shared__ int tmp[1024];
    const int tid = threadIdx.x;
    const int base = tid * 16;
    int loc[16];
    int s = 0;
#pragma unroll
    for (int j = 0; j < 16; j++) { loc[j] = s; s += g_counts[base + j]; }
    tmp[tid] = s;
    __syncthreads();
    for (int o = 1; o < 1024; o <<= 1) {
        int v = (tid >= o) ? tmp[tid - o] : 0;
        __syncthreads();
        tmp[tid] += v;
        __syncthreads();
    }
    int excl = tmp[tid] - s;
#pragma unroll
    for (int j = 0; j < 16; j++) {
        int v = excl + loc[j];
        g_off[base + j] = v;
        g_cursor[base + j] = v;
    }
    if (tid == 1023) g_off[N_DST] = excl + s;
}

__global__ void scatter_kernel(const int* __restrict__ src_idx,
                               const int* __restrict__ dst_idx)
{
    int e = blockIdx.x * blockDim.x + threadIdx.x;
    if (e >= NE) return;
    int s = src_idx[e];
    int d = dst_idx[e];
    const float* el = g_el + s * NH;
    const float* er = g_er + d * NH;
    float4 ev;
    float x;
    x = el[0] + er[0]; ev.x = (x > 0.f) ? x : NEG_SLOPE * x;
    x = el[1] + er[1]; ev.y = (x > 0.f) ? x : NEG_SLOPE * x;
    x = el[2] + er[2]; ev.z = (x > 0.f) ? x : NEG_SLOPE * x;
    x = el[3] + er[3]; ev.w = (x > 0.f) ? x : NEG_SLOPE * x;
    int pos = atomicAdd(&g_cursor[d], 1);
    g_csr_src[pos] = s;
    g_csr_e[pos]   = ev;
}

__global__ void __launch_bounds__(256)
s_kernel(const float* __restrict__ poi_coeff, const int* __restrict__ output_nodes,
         const int* __restrict__ ncounts)
{
    const int lane = threadIdx.x & 31, warp = threadIdx.x >> 5;
    const int d = blockIdx.x * 8 + warp;
    if (d >= N_DST) return;
    int node = output_nodes[d];
    int c = ncounts[node];
    if (c > KNB) c = KNB;
    float p = 0.f;
    for (int j = lane; j < c; j += 32) p += poi_coeff[(size_t)node * KNB + j];
#pragma unroll
    for (int o = 16; o; o >>= 1) p += __shfl_xor_sync(0xffffffffu, p, o);
    if (lane == 0) g_s[d] = p;
}

__global__ void __launch_bounds__(128)
aggregate_kernel(const float* __restrict__ bias, float* __restrict__ out)
{
    const int d    = blockIdx.x;
    const int tid  = threadIdx.x;
    const int lane = tid & 31, warp = tid >> 5;
    const int beg  = g_off[d];
    const int deg  = g_off[d + 1] - beg;

    __shared__ float sa[CAP * 4];
    __shared__ int   ssrc[CAP];
    __shared__ float red[4][4];
    __shared__ float smx[4], sinv[4];

    float m0 = -3e38f, m1 = -3e38f, m2 = -3e38f, m3 = -3e38f;
    for (int e = tid; e < deg; e += 128) {
        float4 v = g_csr_e[beg + e];
        m0 = fmaxf(m0, v.x); m1 = fmaxf(m1, v.y);
        m2 = fmaxf(m2, v.z); m3 = fmaxf(m3, v.w);
    }
#pragma unroll
    for (int o = 16; o; o >>= 1) {
        m0 = fmaxf(m0, __shfl_xor_sync(0xffffffffu, m0, o));
        m1 = fmaxf(m1, __shfl_xor_sync(0xffffffffu, m1, o));
        m2 = fmaxf(m2, __shfl_xor_sync(0xffffffffu, m2, o));
        m3 = fmaxf(m3, __shfl_xor_sync(0xffffffffu, m3, o));
    }
    if (lane == 0) { red[warp][0] = m0; red[warp][1] = m1; red[warp][2] = m2; red[warp][3] = m3; }
    __syncthreads();
    if (tid < 4)
        smx[tid] = fmaxf(fmaxf(red[0][tid], red[1][tid]), fmaxf(red[2][tid], red[3][tid]));
    __syncthreads();
    m0 = smx[0]; m1 = smx[1]; m2 = smx[2]; m3 = smx[3];

    float d0 = 0.f, d1 = 0.f, d2 = 0.f, d3 = 0.f;
    for (int e = tid; e < deg; e += 128) {
        float4 v = g_csr_e[beg + e];
        float w0 = __expf(v.x - m0), w1 = __expf(v.y - m1);
        float w2 = __expf(v.z - m2), w3 = __expf(v.w - m3);
        if (e < CAP) {
            sa[e * 4 + 0] = w0; sa[e * 4 + 1] = w1;
            sa[e * 4 + 2] = w2; sa[e * 4 + 3] = w3;
            ssrc[e] = g_csr_src[beg + e];
        }
        d0 += w0; d1 += w1; d2 += w2; d3 += w3;
    }
#pragma unroll
    for (int o = 16; o; o >>= 1) {
        d0 += __shfl_xor_sync(0xffffffffu, d0, o);
        d1 += __shfl_xor_sync(0xffffffffu, d1, o);
        d2 += __shfl_xor_sync(0xffffffffu, d2, o);
        d3 += __shfl_xor_sync(0xffffffffu, d3, o);
    }
    if (lane == 0) { red[warp][0] = d0; red[warp][1] = d1; red[warp][2] = d2; red[warp][3] = d3; }
    __syncthreads();
    if (tid < 4) {
        float den = red[0][tid] + red[1][tid] + red[2][tid] + red[3][tid];
        sinv[tid] = 1.0f / fmaxf(den, 1e-9f);
    }
    __syncthreads();

    float a0 = 0.f, a1 = 0.f, a2 = 0.f, a3 = 0.f;
    for (int e = 0; e < deg; e++) {
        int s;
        float w0, w1, w2, w3;
        if (e < CAP) {
            s = ssrc[e];
            w0 = sa[e * 4 + 0]; w1 = sa[e * 4 + 1];
            w2 = sa[e * 4 + 2]; w3 = sa[e * 4 + 3];
        } else {
            s = g_csr_src[beg + e];
            float4 v = g_csr_e[beg + e];
            w0 = __expf(v.x - m0); w1 = __expf(v.y - m1);
            w2 = __expf(v.z - m2); w3 = __expf(v.w - m3);
        }
        const float* fs = g_feat_src + (size_t)s * FDIM + tid;
        a0 = fmaf(w0, fs[0],   a0);
        a1 = fmaf(w1, fs[128], a1);
        a2 = fmaf(w2, fs[256], a2);
        a3 = fmaf(w3, fs[384], a3);
    }

    const float sd   = g_s[d];
    const float dist = g_dist[(size_t)d * HIDD + tid] * sd;
    const size_t ob  = (size_t)d * FDIM + tid;
    float accs[4] = {a0 * sinv[0], a1 * sinv[1], a2 * sinv[2], a3 * sinv[3]};
#pragma unroll
    for (int h = 0; h < 4; h++) {
        float x = accs[h] + g_res[ob + h * 128] + bias[h * 128 + tid];
        float eluv = (x > 0.f) ? x : expm1f(x);
        float o = (eluv + dist) * 0.5f;
        out[ob + h * 128] = (o > 0.f) ? o : 0.f;
    }
}

/* ================= launch ================================================= */
extern "C" void kernel_launch(void* const* d_in, const int* in_sizes, int n_in,
                              void* d_out, int out_size)
{
    const float* feat       = (const float*)d_in[0];
    const float* poi_cat    = (const float*)d_in[1];
    const float* poi_coeff  = (const float*)d_in[2];
    const float* fc_w       = (const float*)d_in[3];
    const float* attn_l     = (const float*)d_in[4];
    const float* attn_r     = (const float*)d_in[5];
    const float* bias_p     = (const float*)d_in[6];
    const float* res_w      = (const float*)d_in[7];
    const float* w_w        = (const float*)d_in[8];
    const int*   src_idx    = (const int*)d_in[9];
    const int*   dst_idx    = (const int*)d_in[10];
    const int*   out_nodes  = (const int*)d_in[11];
    const int*   ncounts    = (const int*)d_in[12];
    float*       out        = (float*)d_out;

    cudaFuncSetAttribute(tc_gemm, cudaFuncAttributeMaxDynamicSharedMemorySize, SM_TOTAL);

    zero_counts_kernel<<<N_DST / 256, 256>>>();
    conv_w_kernel<<<256, 256>>>(fc_w, 0);
    conv_w_kernel<<<256, 256>>>(res_w, 1);

    /* GEMM1 (+fused el/er): feat_src = feat @ fc_w^T */
    tc_gemm<<<dim3(4, N_SRC / 128), 256, SM_TOTAL>>>(feat, 0, attn_l, attn_r);
    /* GEMM2: res = feat[:Ndst] @ res_w^T */
    tc_gemm<<<dim3(4, N_DST / 128), 256, SM_TOTAL>>>(feat, 1, attn_l, attn_r);
    /* GEMM3: dist = poi_cat[gather] @ w_w^T */
    sgemm_nt<<<dim3(N_DST / 128, HIDD / 64), 256>>>(poi_cat, w_w, out_nodes, HIDD);

    hist_kernel<<<NE / 256, 256>>>(dst_idx);
    scan_kernel<<<1, 1024>>>();
    scatter_kernel<<<NE / 256, 256>>>(src_idx, dst_idx);
    s_kernel<<<N_DST / 8, 256>>>(poi_coeff, out_nodes, ncounts);
    aggregate_kernel<<<N_DST, 128>>>(bias_p, out);
}

// round 4
// speedup vs baseline: 1.6762x; 1.1861x over previous
#include <cuda_runtime.h>
#include <cuda_fp16.h>
#include <math.h>
#include <stdint.h>

#define N_SRC   65536
#define N_DST   16384
#define NE      262144
#define IN_F    256
#define HIDD    128
#define NH      4
#define FDIM    512      /* NH*HIDD */
#define KNB     50
#define CAP     1024
#define NEG_SLOPE 0.2f

/* padded row: 72 fp16 = 144 B -> 8 consecutive rows hit 8 distinct 16B
   chunks (mod 128): ldmatrix conflict-free. */
#define ASTRIDE_E 72
#define ASTRIDE_B 144
#define TILE_B    (128 * ASTRIDE_B)     /* 18432 */
#define STAGE_B   (3 * TILE_B)          /* A_hi + A_lo + B_hi = 55296 */
#define SM_ELS    (2 * STAGE_B)         /* 110592 */
#define SM_ERS    (SM_ELS + 512)
#define SM_TOTAL  (SM_ERS + 512)        /* 111616 */

/* ================= scratch globals ======================================== */
__device__ float  g_feat_src[(size_t)N_SRC * FDIM];
__device__ float  g_res     [(size_t)N_DST * FDIM];
__device__ float  g_dist    [(size_t)N_DST * HIDD];
__device__ float  g_el      [N_SRC * NH];
__device__ float  g_er      [N_DST * NH];
__device__ float  g_s       [N_DST];
__device__ int    g_counts  [N_DST];
__device__ int    g_off     [N_DST + 1];
__device__ int    g_cursor  [N_DST];
__device__ int    g_csr_src [NE];
__device__ float4 g_csr_e   [NE];
/* pre-converted fp16 images, padded rows: A [chunk(4)][row(65536)][72],
   W [chunk(4)][n(512)][72] */
__device__ __align__(16) __half g_ahi[(size_t)4 * N_SRC * ASTRIDE_E];
__device__ __align__(16) __half g_alo[(size_t)4 * N_SRC * ASTRIDE_E];
__device__ __align__(16) __half g_w1hi[4 * 512 * ASTRIDE_E];
__device__ __align__(16) __half g_w2hi[4 * 512 * ASTRIDE_E];

/* ================= PTX wrappers (arch-generic, sm_80+) ==================== */
__device__ __forceinline__ uint32_t smem_u32(const void* p) {
    uint32_t a;
    asm("{ .reg .u64 t; cvta.to.shared.u64 t, %1; cvt.u32.u64 %0, t; }"
        : "=r"(a) : "l"(p));
    return a;
}
__device__ __forceinline__ void ldsm4(uint32_t* r, uint32_t addr) {
    asm volatile("ldmatrix.sync.aligned.m8n8.x4.shared.b16 {%0,%1,%2,%3}, [%4];"
                 : "=r"(r[0]), "=r"(r[1]), "=r"(r[2]), "=r"(r[3]) : "r"(addr));
}
__device__ __forceinline__ void ldsm2(uint32_t* r, uint32_t addr) {
    asm volatile("ldmatrix.sync.aligned.m8n8.x2.shared.b16 {%0,%1}, [%2];"
                 : "=r"(r[0]), "=r"(r[1]) : "r"(addr));
}
__device__ __forceinline__ void mma16816(float* c, const uint32_t* a, const uint32_t* b) {
    asm volatile("mma.sync.aligned.m16n8k16.row.col.f32.f16.f16.f32 "
                 "{%0,%1,%2,%3}, {%4,%5,%6,%7}, {%8,%9}, {%0,%1,%2,%3};"
                 : "+f"(c[0]), "+f"(c[1]), "+f"(c[2]), "+f"(c[3])
                 : "r"(a[0]), "r"(a[1]), "r"(a[2]), "r"(a[3]),
                   "r"(b[0]), "r"(b[1]));
}
__device__ __forceinline__ void cp16(uint32_t dst, const void* src) {
    asm volatile("cp.async.cg.shared.global [%0], [%1], 16;"
                 :: "r"(dst), "l"(src));
}
#define CP_COMMIT() asm volatile("cp.async.commit_group;" ::: "memory")

/* ================= prep: fp32 -> fp16 hi/lo padded images ================= */
__global__ void conv_a_kernel(const float* __restrict__ feat)
{
    int p = blockIdx.x * blockDim.x + threadIdx.x;     /* N_SRC*128 threads */
    int row = p >> 7;
    int col = (p & 127) * 2;
    int chunk = col >> 6;
    int klocal = col & 63;
    float2 v = *(const float2*)(feat + (size_t)row * IN_F + col);
    __half h0 = __float2half_rn(v.x);
    __half h1 = __float2half_rn(v.y);
    __half l0 = __float2half_rn(v.x - __half2float(h0));
    __half l1 = __float2half_rn(v.y - __half2float(h1));
    size_t off = ((size_t)chunk * N_SRC + row) * ASTRIDE_E + klocal;
    *(__half2*)(g_ahi + off) = __halves2half2(h0, h1);
    *(__half2*)(g_alo + off) = __halves2half2(l0, l1);
}

__global__ void conv_w_kernel(const float* __restrict__ W, int which)
{
    __half* dhi = which ? g_w2hi : g_w1hi;
    int p = blockIdx.x * blockDim.x + threadIdx.x;     /* 512*128 threads */
    int n  = p >> 7;
    int col = (p & 127) * 2;
    int chunk = col >> 6;
    int klocal = col & 63;
    float2 v = *(const float2*)(W + (size_t)n * IN_F + col);
    __half h0 = __float2half_rn(v.x);
    __half h1 = __float2half_rn(v.y);
    size_t off = (size_t)(chunk * 512 + n) * ASTRIDE_E + klocal;
    *(__half2*)(dhi + off) = __halves2half2(h0, h1);
}

/* ================= HMMA GEMM (merged GEMM1+GEMM2) =========================
   out[M,512] = A[M,256] @ W[512,256]^T, fp16 hi/lo 2-pass.
   grid = (4 heads, 512+128 slabs). y<512 -> GEMM1 (+el/er); else GEMM2.    */
__global__ void __launch_bounds__(256, 1)
tc_gemm(const float* __restrict__ attn_l, const float* __restrict__ attn_r)
{
    extern __shared__ unsigned char smem[];
    const uint32_t sb = smem_u32(smem);
    const int tid  = threadIdx.x;
    const int wid  = tid >> 5;
    const int lane = tid & 31;
    const int wm   = wid & 1;
    const int wn   = wid >> 1;
    const int head = blockIdx.x;
    const int which = (blockIdx.y >= 512);
    const int row0  = (which ? (blockIdx.y - 512) : blockIdx.y) * 128;

    float* out = which ? g_res : g_feat_src;
    const __half* whi = which ? g_w2hi : g_w1hi;

    float* els = (float*)(smem + SM_ELS);
    float* ers = (float*)(smem + SM_ERS);
    if (which == 0 && tid < 128) { els[tid] = 0.f; ers[tid] = 0.f; }

    float c[4][4][4];
#pragma unroll
    for (int mt = 0; mt < 4; mt++)
#pragma unroll
        for (int nt = 0; nt < 4; nt++)
#pragma unroll
            for (int j = 0; j < 4; j++) c[mt][nt][j] = 0.f;

    const int lr  = tid >> 1;       /* copy row 0..127  */
    const int seg = tid & 1;        /* 64B half of row  */

    /* issue cp.async loads of one k-chunk into a stage */
    auto load_chunk = [&](int chunk, int stage) {
        const uint32_t st = sb + stage * STAGE_B + (uint32_t)lr * ASTRIDE_B + seg * 64;
        const __half* sa_hi = g_ahi + ((size_t)chunk * N_SRC + row0 + lr) * ASTRIDE_E + seg * 32;
        const __half* sa_lo = g_alo + ((size_t)chunk * N_SRC + row0 + lr) * ASTRIDE_E + seg * 32;
        const __half* sb_hi = whi + (size_t)(chunk * 512 + head * 128 + lr) * ASTRIDE_E + seg * 32;
#pragma unroll
        for (int i = 0; i < 4; i++) {
            cp16(st + i * 16,              sa_hi + i * 8);
            cp16(st + TILE_B + i * 16,     sa_lo + i * 8);
            cp16(st + 2 * TILE_B + i * 16, sb_hi + i * 8);
        }
    };

    load_chunk(0, 0);
    CP_COMMIT();

    for (int chunk = 0; chunk < 4; chunk++) {
        const int s = chunk & 1;
        if (chunk < 3) {
            load_chunk(chunk + 1, 1 - s);
            CP_COMMIT();
            asm volatile("cp.async.wait_group 1;" ::: "memory");
        } else {
            asm volatile("cp.async.wait_group 0;" ::: "memory");
        }
        __syncthreads();

        const uint32_t a_base = sb + s * STAGE_B
                                + (uint32_t)(wm * 64 + (lane & 15)) * ASTRIDE_B
                                + (uint32_t)(lane >> 4) * 16;
        const uint32_t b_base = sb + s * STAGE_B + 2 * TILE_B
                                + (uint32_t)(wn * 32 + (lane & 7)) * ASTRIDE_B
                                + (uint32_t)((lane >> 3) & 1) * 16;
#pragma unroll
        for (int kk = 0; kk < 4; kk++) {
            uint32_t ah[4][4], al[4][4], bh[4][2];
#pragma unroll
            for (int mt = 0; mt < 4; mt++) {
                uint32_t ad = a_base + mt * 16 * ASTRIDE_B + kk * 32;
                ldsm4(ah[mt], ad);
                ldsm4(al[mt], ad + TILE_B);
            }
#pragma unroll
            for (int nt = 0; nt < 4; nt++)
                ldsm2(bh[nt], b_base + nt * 8 * ASTRIDE_B + kk * 32);
#pragma unroll
            for (int mt = 0; mt < 4; mt++)
#pragma unroll
                for (int nt = 0; nt < 4; nt++) {
                    mma16816(c[mt][nt], ah[mt], bh[nt]);
                    mma16816(c[mt][nt], al[mt], bh[nt]);
                }
        }
        __syncthreads();
    }

    /* ---- epilogue: store C; fused el/er for which==0 ---- */
    float2 al2[4], ar2[4];
    if (which == 0) {
#pragma unroll
        for (int nt = 0; nt < 4; nt++) {
            int cg = head * 128 + wn * 32 + nt * 8 + (lane & 3) * 2;
            al2[nt] = *(const float2*)(attn_l + cg);
            ar2[nt] = *(const float2*)(attn_r + cg);
        }
    }
#pragma unroll
    for (int mt = 0; mt < 4; mt++) {
        int r0 = wm * 64 + mt * 16 + (lane >> 2);
        int r1 = r0 + 8;
        float pl0 = 0.f, pl1 = 0.f, pr0 = 0.f, pr1 = 0.f;
#pragma unroll
        for (int nt = 0; nt < 4; nt++) {
            int cl = wn * 32 + nt * 8 + (lane & 3) * 2;
            float2 v0 = make_float2(c[mt][nt][0], c[mt][nt][1]);
            float2 v1 = make_float2(c[mt][nt][2], c[mt][nt][3]);
            *(float2*)(out + (size_t)(row0 + r0) * FDIM + head * 128 + cl) = v0;
            *(float2*)(out + (size_t)(row0 + r1) * FDIM + head * 128 + cl) = v1;
            if (which == 0) {
                pl0 = fmaf(v0.x, al2[nt].x, fmaf(v0.y, al2[nt].y, pl0));
                pl1 = fmaf(v1.x, al2[nt].x, fmaf(v1.y, al2[nt].y, pl1));
                pr0 = fmaf(v0.x, ar2[nt].x, fmaf(v0.y, ar2[nt].y, pr0));
                pr1 = fmaf(v1.x, ar2[nt].x, fmaf(v1.y, ar2[nt].y, pr1));
            }
        }
        if (which == 0) {
#pragma unroll
            for (int o = 1; o <= 2; o <<= 1) {
                pl0 += __shfl_xor_sync(0xffffffffu, pl0, o);
                pl1 += __shfl_xor_sync(0xffffffffu, pl1, o);
                pr0 += __shfl_xor_sync(0xffffffffu, pr0, o);
                pr1 += __shfl_xor_sync(0xffffffffu, pr1, o);
            }
            if ((lane & 3) == 0) {
                atomicAdd(&els[r0], pl0); atomicAdd(&els[r1], pl1);
                atomicAdd(&ers[r0], pr0); atomicAdd(&ers[r1], pr1);
            }
        }
    }
    if (which == 0) {
        __syncthreads();
        if (tid < 128) {
            int grow = row0 + tid;
            g_el[grow * NH + head] = els[tid];
            if (grow < N_DST) g_er[grow * NH + head] = ers[tid];
        }
    }
}

/* ================= SIMT GEMM (gathered GEMM3) ============================= */
__global__ void __launch_bounds__(256)
sgemm_nt(const float* __restrict__ A, const float* __restrict__ B,
         const int* __restrict__ gather, int N)
{
    float* Cbase = g_dist;
    __shared__ float As[16][128];
    __shared__ float Bs[16][64];
    const int tid = threadIdx.x;
    const int m0 = blockIdx.x * 128;
    const int n0 = blockIdx.y * 64;
    const int tm = tid >> 4, tn = tid & 15;
    const int ar = tid >> 2, ac = (tid & 3) * 4;

    int grow0 = m0 + ar, grow1 = m0 + ar + 64;
    if (gather) { grow0 = gather[grow0]; grow1 = gather[grow1]; }
    const float* Arow0 = A + (size_t)grow0 * IN_F;
    const float* Arow1 = A + (size_t)grow1 * IN_F;
    const float* Brow  = B + (size_t)(n0 + ar) * IN_F;

    float acc[8][4];
#pragma unroll
    for (int i = 0; i < 8; i++)
#pragma unroll
        for (int j = 0; j < 4; j++) acc[i][j] = 0.f;

    for (int k0 = 0; k0 < IN_F; k0 += 16) {
        float4 va0 = *(const float4*)(Arow0 + k0 + ac);
        float4 va1 = *(const float4*)(Arow1 + k0 + ac);
        float4 vb  = *(const float4*)(Brow  + k0 + ac);
        As[ac + 0][ar]      = va0.x; As[ac + 1][ar]      = va0.y;
        As[ac + 2][ar]      = va0.z; As[ac + 3][ar]      = va0.w;
        As[ac + 0][ar + 64] = va1.x; As[ac + 1][ar + 64] = va1.y;
        As[ac + 2][ar + 64] = va1.z; As[ac + 3][ar + 64] = va1.w;
        Bs[ac + 0][ar] = vb.x; Bs[ac + 1][ar] = vb.y;
        Bs[ac + 2][ar] = vb.z; Bs[ac + 3][ar] = vb.w;
        __syncthreads();
#pragma unroll
        for (int kk = 0; kk < 16; kk++) {
            float4 a0 = *(const float4*)&As[kk][tm * 8];
            float4 a1 = *(const float4*)&As[kk][tm * 8 + 4];
            float4 b  = *(const float4*)&Bs[kk][tn * 4];
            float av[8] = {a0.x, a0.y, a0.z, a0.w, a1.x, a1.y, a1.z, a1.w};
            float bv[4] = {b.x, b.y, b.z, b.w};
#pragma unroll
            for (int i = 0; i < 8; i++)
#pragma unroll
                for (int j = 0; j < 4; j++)
                    acc[i][j] = fmaf(av[i], bv[j], acc[i][j]);
        }
        __syncthreads();
    }
#pragma unroll
    for (int i = 0; i < 8; i++) {
        float4 v = make_float4(acc[i][0], acc[i][1], acc[i][2], acc[i][3]);
        *(float4*)&Cbase[(size_t)(m0 + tm * 8 + i) * N + n0 + tn * 4] = v;
    }
}

/* ================= CSR build + softmax aggregation (unchanged) ============ */
__global__ void zero_counts_kernel() {
    int i = blockIdx.x * blockDim.x + threadIdx.x;
    if (i < N_DST) g_counts[i] = 0;
}

__global__ void hist_kernel(const int* __restrict__ dst_idx)
{
    int e = blockIdx.x * blockDim.x + threadIdx.x;
    if (e < NE) atomicAdd(&g_counts[dst_idx[e]], 1);
}

__global__ void __launch_bounds__(1024) scan_kernel()
{
    __shared__ int tmp[1024];
    const int tid = threadIdx.x;
    const int base = tid * 16;
    int loc[16];
    int s = 0;
#pragma unroll
    for (int j = 0; j < 16; j++) { loc[j] = s; s += g_counts[base + j]; }
    tmp[tid] = s;
    __syncthreads();
    for (int o = 1; o < 1024; o <<= 1) {
        int v = (tid >= o) ? tmp[tid - o] : 0;
        __syncthreads();
        tmp[tid] += v;
        __syncthreads();
    }
    int excl = tmp[tid] - s;
#pragma unroll
    for (int j = 0; j < 16; j++) {
        int v = excl + loc[j];
        g_off[base + j] = v;
        g_cursor[base + j] = v;
    }
    if (tid == 1023) g_off[N_DST] = excl + s;
}

__global__ void scatter_kernel(const int* __restrict__ src_idx,
                               const int* __restrict__ dst_idx)
{
    int e = blockIdx.x * blockDim.x + threadIdx.x;
    if (e >= NE) return;
    int s = src_idx[e];
    int d = dst_idx[e];
    const float* el = g_el + s * NH;
    const float* er = g_er + d * NH;
    float4 ev;
    float x;
    x = el[0] + er[0]; ev.x = (x > 0.f) ? x : NEG_SLOPE * x;
    x = el[1] + er[1]; ev.y = (x > 0.f) ? x : NEG_SLOPE * x;
    x = el[2] + er[2]; ev.z = (x > 0.f) ? x : NEG_SLOPE * x;
    x = el[3] + er[3]; ev.w = (x > 0.f) ? x : NEG_SLOPE * x;
    int pos = atomicAdd(&g_cursor[d], 1);
    g_csr_src[pos] = s;
    g_csr_e[pos]   = ev;
}

__global__ void __launch_bounds__(256)
s_kernel(const float* __restrict__ poi_coeff, const int* __restrict__ output_nodes,
         const int* __restrict__ ncounts)
{
    const int lane = threadIdx.x & 31, warp = threadIdx.x >> 5;
    const int d = blockIdx.x * 8 + warp;
    if (d >= N_DST) return;
    int node = output_nodes[d];
    int c = ncounts[node];
    if (c > KNB) c = KNB;
    float p = 0.f;
    for (int j = lane; j < c; j += 32) p += poi_coeff[(size_t)node * KNB + j];
#pragma unroll
    for (int o = 16; o; o >>= 1) p += __shfl_xor_sync(0xffffffffu, p, o);
    if (lane == 0) g_s[d] = p;
}

__global__ void __launch_bounds__(128)
aggregate_kernel(const float* __restrict__ bias, float* __restrict__ out)
{
    const int d    = blockIdx.x;
    const int tid  = threadIdx.x;
    const int lane = tid & 31, warp = tid >> 5;
    const int beg  = g_off[d];
    const int deg  = g_off[d + 1] - beg;

    __shared__ float sa[CAP * 4];
    __shared__ int   ssrc[CAP];
    __shared__ float red[4][4];
    __shared__ float smx[4], sinv[4];

    float m0 = -3e38f, m1 = -3e38f, m2 = -3e38f, m3 = -3e38f;
    for (int e = tid; e < deg; e += 128) {
        float4 v = g_csr_e[beg + e];
        m0 = fmaxf(m0, v.x); m1 = fmaxf(m1, v.y);
        m2 = fmaxf(m2, v.z); m3 = fmaxf(m3, v.w);
    }
#pragma unroll
    for (int o = 16; o; o >>= 1) {
        m0 = fmaxf(m0, __shfl_xor_sync(0xffffffffu, m0, o));
        m1 = fmaxf(m1, __shfl_xor_sync(0xffffffffu, m1, o));
        m2 = fmaxf(m2, __shfl_xor_sync(0xffffffffu, m2, o));
        m3 = fmaxf(m3, __shfl_xor_sync(0xffffffffu, m3, o));
    }
    if (lane == 0) { red[warp][0] = m0; red[warp][1] = m1; red[warp][2] = m2; red[warp][3] = m3; }
    __syncthreads();
    if (tid < 4)
        smx[tid] = fmaxf(fmaxf(red[0][tid], red[1][tid]), fmaxf(red[2][tid], red[3][tid]));
    __syncthreads();
    m0 = smx[0]; m1 = smx[1]; m2 = smx[2]; m3 = smx[3];

    float d0 = 0.f, d1 = 0.f, d2 = 0.f, d3 = 0.f;
    for (int e = tid; e < deg; e += 128) {
        float4 v = g_csr_e[beg + e];
        float w0 = __expf(v.x - m0), w1 = __expf(v.y - m1);
        float w2 = __expf(v.z - m2), w3 = __expf(v.w - m3);
        if (e < CAP) {
            sa[e * 4 + 0] = w0; sa[e * 4 + 1] = w1;
            sa[e * 4 + 2] = w2; sa[e * 4 + 3] = w3;
            ssrc[e] = g_csr_src[beg + e];
        }
        d0 += w0; d1 += w1; d2 += w2; d3 += w3;
    }
#pragma unroll
    for (int o = 16; o; o >>= 1) {
        d0 += __shfl_xor_sync(0xffffffffu, d0, o);
        d1 += __shfl_xor_sync(0xffffffffu, d1, o);
        d2 += __shfl_xor_sync(0xffffffffu, d2, o);
        d3 += __shfl_xor_sync(0xffffffffu, d3, o);
    }
    if (lane == 0) { red[warp][0] = d0; red[warp][1] = d1; red[warp][2] = d2; red[warp][3] = d3; }
    __syncthreads();
    if (tid < 4) {
        float den = red[0][tid] + red[1][tid] + red[2][tid] + red[3][tid];
        sinv[tid] = 1.0f / fmaxf(den, 1e-9f);
    }
    __syncthreads();

    float a0 = 0.f, a1 = 0.f, a2 = 0.f, a3 = 0.f;
    for (int e = 0; e < deg; e++) {
        int s;
        float w0, w1, w2, w3;
        if (e < CAP) {
            s = ssrc[e];
            w0 = sa[e * 4 + 0]; w1 = sa[e * 4 + 1];
            w2 = sa[e * 4 + 2]; w3 = sa[e * 4 + 3];
        } else {
            s = g_csr_src[beg + e];
            float4 v = g_csr_e[beg + e];
            w0 = __expf(v.x - m0); w1 = __expf(v.y - m1);
            w2 = __expf(v.z - m2); w3 = __expf(v.w - m3);
        }
        const float* fs = g_feat_src + (size_t)s * FDIM + tid;
        a0 = fmaf(w0, fs[0],   a0);
        a1 = fmaf(w1, fs[128], a1);
        a2 = fmaf(w2, fs[256], a2);
        a3 = fmaf(w3, fs[384], a3);
    }

    const float sd   = g_s[d];
    const float dist = g_dist[(size_t)d * HIDD + tid] * sd;
    const size_t ob  = (size_t)d * FDIM + tid;
    float accs[4] = {a0 * sinv[0], a1 * sinv[1], a2 * sinv[2], a3 * sinv[3]};
#pragma unroll
    for (int h = 0; h < 4; h++) {
        float x = accs[h] + g_res[ob + h * 128] + bias[h * 128 + tid];
        float eluv = (x > 0.f) ? x : expm1f(x);
        float o = (eluv + dist) * 0.5f;
        out[ob + h * 128] = (o > 0.f) ? o : 0.f;
    }
}

/* ================= launch ================================================= */
extern "C" void kernel_launch(void* const* d_in, const int* in_sizes, int n_in,
                              void* d_out, int out_size)
{
    const float* feat       = (const float*)d_in[0];
    const float* poi_cat    = (const float*)d_in[1];
    const float* poi_coeff  = (const float*)d_in[2];
    const float* fc_w       = (const float*)d_in[3];
    const float* attn_l     = (const float*)d_in[4];
    const float* attn_r     = (const float*)d_in[5];
    const float* bias_p     = (const float*)d_in[6];
    const float* res_w      = (const float*)d_in[7];
    const float* w_w        = (const float*)d_in[8];
    const int*   src_idx    = (const int*)d_in[9];
    const int*   dst_idx    = (const int*)d_in[10];
    const int*   out_nodes  = (const int*)d_in[11];
    const int*   ncounts    = (const int*)d_in[12];
    float*       out        = (float*)d_out;

    cudaFuncSetAttribute(tc_gemm, cudaFuncAttributeMaxDynamicSharedMemorySize, SM_TOTAL);

    zero_counts_kernel<<<N_DST / 256, 256>>>();
    conv_a_kernel<<<N_SRC * 128 / 256, 256>>>(feat);
    conv_w_kernel<<<256, 256>>>(fc_w, 0);
    conv_w_kernel<<<256, 256>>>(res_w, 1);

    /* merged GEMM1 (+fused el/er) and GEMM2 */
    tc_gemm<<<dim3(4, 512 + 128), 256, SM_TOTAL>>>(attn_l, attn_r);
    /* GEMM3: dist = poi_cat[gather] @ w_w^T */
    sgemm_nt<<<dim3(N_DST / 128, HIDD / 64), 256>>>(poi_cat, w_w, out_nodes, HIDD);

    hist_kernel<<<NE / 256, 256>>>(dst_idx);
    scan_kernel<<<1, 1024>>>();
    scatter_kernel<<<NE / 256, 256>>>(src_idx, dst_idx);
    s_kernel<<<N_DST / 8, 256>>>(poi_coeff, out_nodes, ncounts);
    aggregate_kernel<<<N_DST, 128>>>(bias_p, out);
}

// round 5
// speedup vs baseline: 1.9589x; 1.1686x over previous
#include <cuda_runtime.h>
#include <cuda_fp16.h>
#include <math.h>
#include <stdint.h>

#define N_SRC   65536
#define N_DST   16384
#define NE      262144
#define IN_F    256
#define HIDD    128
#define NH      4
#define FDIM    512      /* NH*HIDD */
#define KNB     50
#define CAP     1024
#define NEG_SLOPE 0.2f

/* padded row: 72 fp16 = 144 B -> 8 consecutive rows hit 8 distinct 16B
   chunks (mod 128): ldmatrix conflict-free. */
#define ASTRIDE_E 72
#define ASTRIDE_B 144
#define TILE_B    (128 * ASTRIDE_B)     /* 18432 */
#define STAGE_B   (3 * TILE_B)          /* A_hi + A_lo + B_hi = 55296 */
#define SM_ELS    (2 * STAGE_B)         /* 110592 */
#define SM_ERS    (SM_ELS + 512)
#define SM_TOTAL  (SM_ERS + 512)        /* 111616 */

/* ================= scratch globals ======================================== */
__device__ __half g_feat_h[(size_t)N_SRC * FDIM];   /* 64 MB fp16 */
__device__ __half g_res_h [(size_t)N_DST * FDIM];   /* 16 MB fp16 */
__device__ float  g_dist   [(size_t)N_DST * HIDD];
__device__ float  g_el     [N_SRC * NH];
__device__ float  g_er     [N_DST * NH];
__device__ float  g_s      [N_DST];
__device__ int    g_counts [N_DST];
__device__ int    g_off    [N_DST + 1];
__device__ int    g_cursor [N_DST];
__device__ int    g_csr_src[NE];
__device__ float4 g_csr_e  [NE];
/* pre-converted fp16 images, padded rows */
__device__ __align__(16) __half g_ahi[(size_t)4 * N_SRC * ASTRIDE_E];
__device__ __align__(16) __half g_alo[(size_t)4 * N_SRC * ASTRIDE_E];
__device__ __align__(16) __half g_w1hi[4 * 512 * ASTRIDE_E];
__device__ __align__(16) __half g_w2hi[4 * 512 * ASTRIDE_E];

/* ================= PTX wrappers (arch-generic, sm_80+) ==================== */
__device__ __forceinline__ uint32_t smem_u32(const void* p) {
    uint32_t a;
    asm("{ .reg .u64 t; cvta.to.shared.u64 t, %1; cvt.u32.u64 %0, t; }"
        : "=r"(a) : "l"(p));
    return a;
}
__device__ __forceinline__ void ldsm4(uint32_t* r, uint32_t addr) {
    asm volatile("ldmatrix.sync.aligned.m8n8.x4.shared.b16 {%0,%1,%2,%3}, [%4];"
                 : "=r"(r[0]), "=r"(r[1]), "=r"(r[2]), "=r"(r[3]) : "r"(addr));
}
__device__ __forceinline__ void ldsm2(uint32_t* r, uint32_t addr) {
    asm volatile("ldmatrix.sync.aligned.m8n8.x2.shared.b16 {%0,%1}, [%2];"
                 : "=r"(r[0]), "=r"(r[1]) : "r"(addr));
}
__device__ __forceinline__ void mma16816(float* c, const uint32_t* a, const uint32_t* b) {
    asm volatile("mma.sync.aligned.m16n8k16.row.col.f32.f16.f16.f32 "
                 "{%0,%1,%2,%3}, {%4,%5,%6,%7}, {%8,%9}, {%0,%1,%2,%3};"
                 : "+f"(c[0]), "+f"(c[1]), "+f"(c[2]), "+f"(c[3])
                 : "r"(a[0]), "r"(a[1]), "r"(a[2]), "r"(a[3]),
                   "r"(b[0]), "r"(b[1]));
}
__device__ __forceinline__ void cp16(uint32_t dst, const void* src) {
    asm volatile("cp.async.cg.shared.global [%0], [%1], 16;"
                 :: "r"(dst), "l"(src));
}
#define CP_COMMIT() asm volatile("cp.async.commit_group;" ::: "memory")

/* ================= prep: fp32 -> fp16 hi/lo padded images ================= */
__global__ void conv_a_kernel(const float* __restrict__ feat)
{
    int p = blockIdx.x * blockDim.x + threadIdx.x;
    int row = p >> 7;
    int col = (p & 127) * 2;
    int chunk = col >> 6;
    int klocal = col & 63;
    float2 v = *(const float2*)(feat + (size_t)row * IN_F + col);
    __half h0 = __float2half_rn(v.x);
    __half h1 = __float2half_rn(v.y);
    __half l0 = __float2half_rn(v.x - __half2float(h0));
    __half l1 = __float2half_rn(v.y - __half2float(h1));
    size_t off = ((size_t)chunk * N_SRC + row) * ASTRIDE_E + klocal;
    *(__half2*)(g_ahi + off) = __halves2half2(h0, h1);
    *(__half2*)(g_alo + off) = __halves2half2(l0, l1);
}

__global__ void conv_w_kernel(const float* __restrict__ W, int which)
{
    __half* dhi = which ? g_w2hi : g_w1hi;
    int p = blockIdx.x * blockDim.x + threadIdx.x;
    int n  = p >> 7;
    int col = (p & 127) * 2;
    int chunk = col >> 6;
    int klocal = col & 63;
    float2 v = *(const float2*)(W + (size_t)n * IN_F + col);
    size_t off = (size_t)(chunk * 512 + n) * ASTRIDE_E + klocal;
    *(__half2*)(dhi + off) = __floats2half2_rn(v.x, v.y);
}

/* ================= HMMA GEMM (merged GEMM1+GEMM2) =========================
   out[M,512](fp16) = A[M,256] @ W[512,256]^T, fp16 hi/lo 2-pass.
   grid = (4 heads, 512+128 slabs). y<512 -> GEMM1 (+el/er); else GEMM2.    */
__global__ void __launch_bounds__(256, 1)
tc_gemm(const float* __restrict__ attn_l, const float* __restrict__ attn_r)
{
    extern __shared__ unsigned char smem[];
    const uint32_t sb = smem_u32(smem);
    const int tid  = threadIdx.x;
    const int wid  = tid >> 5;
    const int lane = tid & 31;
    const int wm   = wid & 1;
    const int wn   = wid >> 1;
    const int head = blockIdx.x;
    const int which = (blockIdx.y >= 512);
    const int row0  = (which ? (blockIdx.y - 512) : blockIdx.y) * 128;

    __half* outh = which ? g_res_h : g_feat_h;
    const __half* whi = which ? g_w2hi : g_w1hi;

    float* els = (float*)(smem + SM_ELS);
    float* ers = (float*)(smem + SM_ERS);
    if (which == 0 && tid < 128) { els[tid] = 0.f; ers[tid] = 0.f; }

    float c[4][4][4];
#pragma unroll
    for (int mt = 0; mt < 4; mt++)
#pragma unroll
        for (int nt = 0; nt < 4; nt++)
#pragma unroll
            for (int j = 0; j < 4; j++) c[mt][nt][j] = 0.f;

    const int lr  = tid >> 1;
    const int seg = tid & 1;

    auto load_chunk = [&](int chunk, int stage) {
        const uint32_t st = sb + stage * STAGE_B + (uint32_t)lr * ASTRIDE_B + seg * 64;
        const __half* sa_hi = g_ahi + ((size_t)chunk * N_SRC + row0 + lr) * ASTRIDE_E + seg * 32;
        const __half* sa_lo = g_alo + ((size_t)chunk * N_SRC + row0 + lr) * ASTRIDE_E + seg * 32;
        const __half* sb_hi = whi + (size_t)(chunk * 512 + head * 128 + lr) * ASTRIDE_E + seg * 32;
#pragma unroll
        for (int i = 0; i < 4; i++) {
            cp16(st + i * 16,              sa_hi + i * 8);
            cp16(st + TILE_B + i * 16,     sa_lo + i * 8);
            cp16(st + 2 * TILE_B + i * 16, sb_hi + i * 8);
        }
    };

    load_chunk(0, 0);
    CP_COMMIT();

    for (int chunk = 0; chunk < 4; chunk++) {
        const int s = chunk & 1;
        if (chunk < 3) {
            load_chunk(chunk + 1, 1 - s);
            CP_COMMIT();
            asm volatile("cp.async.wait_group 1;" ::: "memory");
        } else {
            asm volatile("cp.async.wait_group 0;" ::: "memory");
        }
        __syncthreads();

        const uint32_t a_base = sb + s * STAGE_B
                                + (uint32_t)(wm * 64 + (lane & 15)) * ASTRIDE_B
                                + (uint32_t)(lane >> 4) * 16;
        const uint32_t b_base = sb + s * STAGE_B + 2 * TILE_B
                                + (uint32_t)(wn * 32 + (lane & 7)) * ASTRIDE_B
                                + (uint32_t)((lane >> 3) & 1) * 16;
#pragma unroll
        for (int kk = 0; kk < 4; kk++) {
            uint32_t ah[4][4], al[4][4], bh[4][2];
#pragma unroll
            for (int mt = 0; mt < 4; mt++) {
                uint32_t ad = a_base + mt * 16 * ASTRIDE_B + kk * 32;
                ldsm4(ah[mt], ad);
                ldsm4(al[mt], ad + TILE_B);
            }
#pragma unroll
            for (int nt = 0; nt < 4; nt++)
                ldsm2(bh[nt], b_base + nt * 8 * ASTRIDE_B + kk * 32);
#pragma unroll
            for (int mt = 0; mt < 4; mt++)
#pragma unroll
                for (int nt = 0; nt < 4; nt++) {
                    mma16816(c[mt][nt], ah[mt], bh[nt]);
                    mma16816(c[mt][nt], al[mt], bh[nt]);
                }
        }
        __syncthreads();
    }

    /* ---- epilogue: store C (fp16); fused el/er for which==0 ---- */
    float2 al2[4], ar2[4];
    if (which == 0) {
#pragma unroll
        for (int nt = 0; nt < 4; nt++) {
            int cg = head * 128 + wn * 32 + nt * 8 + (lane & 3) * 2;
            al2[nt] = *(const float2*)(attn_l + cg);
            ar2[nt] = *(const float2*)(attn_r + cg);
        }
    }
#pragma unroll
    for (int mt = 0; mt < 4; mt++) {
        int r0 = wm * 64 + mt * 16 + (lane >> 2);
        int r1 = r0 + 8;
        float pl0 = 0.f, pl1 = 0.f, pr0 = 0.f, pr1 = 0.f;
#pragma unroll
        for (int nt = 0; nt < 4; nt++) {
            int cl = wn * 32 + nt * 8 + (lane & 3) * 2;
            float2 v0 = make_float2(c[mt][nt][0], c[mt][nt][1]);
            float2 v1 = make_float2(c[mt][nt][2], c[mt][nt][3]);
            *(__half2*)(outh + (size_t)(row0 + r0) * FDIM + head * 128 + cl) =
                __floats2half2_rn(v0.x, v0.y);
            *(__half2*)(outh + (size_t)(row0 + r1) * FDIM + head * 128 + cl) =
                __floats2half2_rn(v1.x, v1.y);
            if (which == 0) {
                pl0 = fmaf(v0.x, al2[nt].x, fmaf(v0.y, al2[nt].y, pl0));
                pl1 = fmaf(v1.x, al2[nt].x, fmaf(v1.y, al2[nt].y, pl1));
                pr0 = fmaf(v0.x, ar2[nt].x, fmaf(v0.y, ar2[nt].y, pr0));
                pr1 = fmaf(v1.x, ar2[nt].x, fmaf(v1.y, ar2[nt].y, pr1));
            }
        }
        if (which == 0) {
#pragma unroll
            for (int o = 1; o <= 2; o <<= 1) {
                pl0 += __shfl_xor_sync(0xffffffffu, pl0, o);
                pl1 += __shfl_xor_sync(0xffffffffu, pl1, o);
                pr0 += __shfl_xor_sync(0xffffffffu, pr0, o);
                pr1 += __shfl_xor_sync(0xffffffffu, pr1, o);
            }
            if ((lane & 3) == 0) {
                atomicAdd(&els[r0], pl0); atomicAdd(&els[r1], pl1);
                atomicAdd(&ers[r0], pr0); atomicAdd(&ers[r1], pr1);
            }
        }
    }
    if (which == 0) {
        __syncthreads();
        if (tid < 128) {
            int grow = row0 + tid;
            g_el[grow * NH + head] = els[tid];
            if (grow < N_DST) g_er[grow * NH + head] = ers[tid];
        }
    }
}

/* ================= SIMT GEMM (gathered GEMM3) ============================= */
__global__ void __launch_bounds__(256)
sgemm_nt(const float* __restrict__ A, const float* __restrict__ B,
         const int* __restrict__ gather, int N)
{
    float* Cbase = g_dist;
    __shared__ float As[16][128];
    __shared__ float Bs[16][64];
    const int tid = threadIdx.x;
    const int m0 = blockIdx.x * 128;
    const int n0 = blockIdx.y * 64;
    const int tm = tid >> 4, tn = tid & 15;
    const int ar = tid >> 2, ac = (tid & 3) * 4;

    int grow0 = m0 + ar, grow1 = m0 + ar + 64;
    if (gather) { grow0 = gather[grow0]; grow1 = gather[grow1]; }
    const float* Arow0 = A + (size_t)grow0 * IN_F;
    const float* Arow1 = A + (size_t)grow1 * IN_F;
    const float* Brow  = B + (size_t)(n0 + ar) * IN_F;

    float acc[8][4];
#pragma unroll
    for (int i = 0; i < 8; i++)
#pragma unroll
        for (int j = 0; j < 4; j++) acc[i][j] = 0.f;

    for (int k0 = 0; k0 < IN_F; k0 += 16) {
        float4 va0 = *(const float4*)(Arow0 + k0 + ac);
        float4 va1 = *(const float4*)(Arow1 + k0 + ac);
        float4 vb  = *(const float4*)(Brow  + k0 + ac);
        As[ac + 0][ar]      = va0.x; As[ac + 1][ar]      = va0.y;
        As[ac + 2][ar]      = va0.z; As[ac + 3][ar]      = va0.w;
        As[ac + 0][ar + 64] = va1.x; As[ac + 1][ar + 64] = va1.y;
        As[ac + 2][ar + 64] = va1.z; As[ac + 3][ar + 64] = va1.w;
        Bs[ac + 0][ar] = vb.x; Bs[ac + 1][ar] = vb.y;
        Bs[ac + 2][ar] = vb.z; Bs[ac + 3][ar] = vb.w;
        __syncthreads();
#pragma unroll
        for (int kk = 0; kk < 16; kk++) {
            float4 a0 = *(const float4*)&As[kk][tm * 8];
            float4 a1 = *(const float4*)&As[kk][tm * 8 + 4];
            float4 b  = *(const float4*)&Bs[kk][tn * 4];
            float av[8] = {a0.x, a0.y, a0.z, a0.w, a1.x, a1.y, a1.z, a1.w};
            float bv[4] = {b.x, b.y, b.z, b.w};
#pragma unroll
            for (int i = 0; i < 8; i++)
#pragma unroll
                for (int j = 0; j < 4; j++)
                    acc[i][j] = fmaf(av[i], bv[j], acc[i][j]);
        }
        __syncthreads();
    }
#pragma unroll
    for (int i = 0; i < 8; i++) {
        float4 v = make_float4(acc[i][0], acc[i][1], acc[i][2], acc[i][3]);
        *(float4*)&Cbase[(size_t)(m0 + tm * 8 + i) * N + n0 + tn * 4] = v;
    }
}

/* ================= CSR build ============================================== */
__global__ void zero_counts_kernel() {
    int i = blockIdx.x * blockDim.x + threadIdx.x;
    if (i < N_DST) g_counts[i] = 0;
}

__global__ void hist_kernel(const int* __restrict__ dst_idx)
{
    int e = blockIdx.x * blockDim.x + threadIdx.x;
    if (e < NE) atomicAdd(&g_counts[dst_idx[e]], 1);
}

__global__ void __launch_bounds__(1024) scan_kernel()
{
    __shared__ int tmp[1024];
    const int tid = threadIdx.x;
    const int base = tid * 16;
    int loc[16];
    int s = 0;
#pragma unroll
    for (int j = 0; j < 16; j++) { loc[j] = s; s += g_counts[base + j]; }
    tmp[tid] = s;
    __syncthreads();
    for (int o = 1; o < 1024; o <<= 1) {
        int v = (tid >= o) ? tmp[tid - o] : 0;
        __syncthreads();
        tmp[tid] += v;
        __syncthreads();
    }
    int excl = tmp[tid] - s;
#pragma unroll
    for (int j = 0; j < 16; j++) {
        int v = excl + loc[j];
        g_off[base + j] = v;
        g_cursor[base + j] = v;
    }
    if (tid == 1023) g_off[N_DST] = excl + s;
}

__global__ void scatter_kernel(const int* __restrict__ src_idx,
                               const int* __restrict__ dst_idx)
{
    int e = blockIdx.x * blockDim.x + threadIdx.x;
    if (e >= NE) return;
    int s = src_idx[e];
    int d = dst_idx[e];
    const float* el = g_el + s * NH;
    const float* er = g_er + d * NH;
    float4 ev;
    float x;
    x = el[0] + er[0]; ev.x = (x > 0.f) ? x : NEG_SLOPE * x;
    x = el[1] + er[1]; ev.y = (x > 0.f) ? x : NEG_SLOPE * x;
    x = el[2] + er[2]; ev.z = (x > 0.f) ? x : NEG_SLOPE * x;
    x = el[3] + er[3]; ev.w = (x > 0.f) ? x : NEG_SLOPE * x;
    int pos = atomicAdd(&g_cursor[d], 1);
    g_csr_src[pos] = s;
    g_csr_e[pos]   = ev;
}

__global__ void __launch_bounds__(256)
s_kernel(const float* __restrict__ poi_coeff, const int* __restrict__ output_nodes,
         const int* __restrict__ ncounts)
{
    const int lane = threadIdx.x & 31, warp = threadIdx.x >> 5;
    const int d = blockIdx.x * 8 + warp;
    if (d >= N_DST) return;
    int node = output_nodes[d];
    int c = ncounts[node];
    if (c > KNB) c = KNB;
    float p = 0.f;
    for (int j = lane; j < c; j += 32) p += poi_coeff[(size_t)node * KNB + j];
#pragma unroll
    for (int o = 16; o; o >>= 1) p += __shfl_xor_sync(0xffffffffu, p, o);
    if (lane == 0) g_s[d] = p;
}

/* ================= per-dst softmax + aggregation (fp16 gather) ============ */
__global__ void __launch_bounds__(128)
aggregate_kernel(const float* __restrict__ bias, float* __restrict__ out)
{
    const int d    = blockIdx.x;
    const int tid  = threadIdx.x;
    const int lane = tid & 31, warp = tid >> 5;
    const int beg  = g_off[d];
    const int deg  = g_off[d + 1] - beg;

    __shared__ float sa[CAP * 4];
    __shared__ int   ssrc[CAP];
    __shared__ float red[4][4];
    __shared__ float smx[4], sinv[4];

    /* ---- pass 1: per-head max ---- */
    float m0 = -3e38f, m1 = -3e38f, m2 = -3e38f, m3 = -3e38f;
    for (int e = tid; e < deg; e += 128) {
        float4 v = g_csr_e[beg + e];
        m0 = fmaxf(m0, v.x); m1 = fmaxf(m1, v.y);
        m2 = fmaxf(m2, v.z); m3 = fmaxf(m3, v.w);
    }
#pragma unroll
    for (int o = 16; o; o >>= 1) {
        m0 = fmaxf(m0, __shfl_xor_sync(0xffffffffu, m0, o));
        m1 = fmaxf(m1, __shfl_xor_sync(0xffffffffu, m1, o));
        m2 = fmaxf(m2, __shfl_xor_sync(0xffffffffu, m2, o));
        m3 = fmaxf(m3, __shfl_xor_sync(0xffffffffu, m3, o));
    }
    if (lane == 0) { red[warp][0] = m0; red[warp][1] = m1; red[warp][2] = m2; red[warp][3] = m3; }
    __syncthreads();
    if (tid < 4)
        smx[tid] = fmaxf(fmaxf(red[0][tid], red[1][tid]), fmaxf(red[2][tid], red[3][tid]));
    __syncthreads();
    m0 = smx[0]; m1 = smx[1]; m2 = smx[2]; m3 = smx[3];

    /* ---- pass 2: exp + denom ---- */
    float d0 = 0.f, d1 = 0.f, d2 = 0.f, d3 = 0.f;
    for (int e = tid; e < deg; e += 128) {
        float4 v = g_csr_e[beg + e];
        float w0 = __expf(v.x - m0), w1 = __expf(v.y - m1);
        float w2 = __expf(v.z - m2), w3 = __expf(v.w - m3);
        if (e < CAP) {
            sa[e * 4 + 0] = w0; sa[e * 4 + 1] = w1;
            sa[e * 4 + 2] = w2; sa[e * 4 + 3] = w3;
            ssrc[e] = g_csr_src[beg + e];
        }
        d0 += w0; d1 += w1; d2 += w2; d3 += w3;
    }
#pragma unroll
    for (int o = 16; o; o >>= 1) {
        d0 += __shfl_xor_sync(0xffffffffu, d0, o);
        d1 += __shfl_xor_sync(0xffffffffu, d1, o);
        d2 += __shfl_xor_sync(0xffffffffu, d2, o);
        d3 += __shfl_xor_sync(0xffffffffu, d3, o);
    }
    if (lane == 0) { red[warp][0] = d0; red[warp][1] = d1; red[warp][2] = d2; red[warp][3] = d3; }
    __syncthreads();
    if (tid < 4) {
        float den = red[0][tid] + red[1][tid] + red[2][tid] + red[3][tid];
        sinv[tid] = 1.0f / fmaxf(den, 1e-9f);
    }
    __syncthreads();

    /* ---- pass 3: thread owns 4 dims of one head; 8B fp16 gather/edge ---- */
    const int head = tid >> 5;          /* 0..3  */
    const int q4   = (tid & 31) * 4;    /* dim base within head */
    const int hq   = head * 128 + q4;
    float a0 = 0.f, a1 = 0.f, a2 = 0.f, a3 = 0.f;
    const float mh = (head == 0) ? m0 : (head == 1) ? m1 : (head == 2) ? m2 : m3;
    for (int e = 0; e < deg; e++) {
        int s;
        float w;
        if (e < CAP) {
            s = ssrc[e];
            w = sa[e * 4 + head];
        } else {
            s = g_csr_src[beg + e];
            const float* ep = (const float*)&g_csr_e[beg + e];
            w = __expf(ep[head] - mh);
        }
        uint2 raw = *(const uint2*)(g_feat_h + (size_t)s * FDIM + hq);
        float2 f0 = __half22float2(*(__half2*)&raw.x);
        float2 f1 = __half22float2(*(__half2*)&raw.y);
        a0 = fmaf(w, f0.x, a0);
        a1 = fmaf(w, f0.y, a1);
        a2 = fmaf(w, f1.x, a2);
        a3 = fmaf(w, f1.y, a3);
    }

    /* ---- epilogue: elu(rst + res + bias), +dist*s, /2, relu ---- */
    const float sd = g_s[d];
    const float wi = sinv[head];
    float4 dv = *(const float4*)(g_dist + (size_t)d * HIDD + q4);
    float4 bv = *(const float4*)(bias + hq);
    uint2 rr = *(const uint2*)(g_res_h + (size_t)d * FDIM + hq);
    float2 r0 = __half22float2(*(__half2*)&rr.x);
    float2 r1 = __half22float2(*(__half2*)&rr.y);
    float acc[4] = {a0 * wi, a1 * wi, a2 * wi, a3 * wi};
    float res[4] = {r0.x, r0.y, r1.x, r1.y};
    float dst[4] = {dv.x * sd, dv.y * sd, dv.z * sd, dv.w * sd};
    float bia[4] = {bv.x, bv.y, bv.z, bv.w};
    float4 ov;
    float* po = (float*)&ov;
#pragma unroll
    for (int j = 0; j < 4; j++) {
        float x = acc[j] + res[j] + bia[j];
        float eluv = (x > 0.f) ? x : expm1f(x);
        float o = (eluv + dst[j]) * 0.5f;
        po[j] = (o > 0.f) ? o : 0.f;
    }
    *(float4*)(out + (size_t)d * FDIM + hq) = ov;
}

/* ================= launch ================================================= */
extern "C" void kernel_launch(void* const* d_in, const int* in_sizes, int n_in,
                              void* d_out, int out_size)
{
    const float* feat       = (const float*)d_in[0];
    const float* poi_cat    = (const float*)d_in[1];
    const float* poi_coeff  = (const float*)d_in[2];
    const float* fc_w       = (const float*)d_in[3];
    const float* attn_l     = (const float*)d_in[4];
    const float* attn_r     = (const float*)d_in[5];
    const float* bias_p     = (const float*)d_in[6];
    const float* res_w      = (const float*)d_in[7];
    const float* w_w        = (const float*)d_in[8];
    const int*   src_idx    = (const int*)d_in[9];
    const int*   dst_idx    = (const int*)d_in[10];
    const int*   out_nodes  = (const int*)d_in[11];
    const int*   ncounts    = (const int*)d_in[12];
    float*       out        = (float*)d_out;

    cudaFuncSetAttribute(tc_gemm, cudaFuncAttributeMaxDynamicSharedMemorySize, SM_TOTAL);

    zero_counts_kernel<<<N_DST / 256, 256>>>();
    conv_a_kernel<<<N_SRC * 128 / 256, 256>>>(feat);
    conv_w_kernel<<<256, 256>>>(fc_w, 0);
    conv_w_kernel<<<256, 256>>>(res_w, 1);

    /* merged GEMM1 (+fused el/er) and GEMM2 */
    tc_gemm<<<dim3(4, 512 + 128), 256, SM_TOTAL>>>(attn_l, attn_r);
    /* GEMM3: dist = poi_cat[gather] @ w_w^T */
    sgemm_nt<<<dim3(N_DST / 128, HIDD / 64), 256>>>(poi_cat, w_w, out_nodes, HIDD);

    hist_kernel<<<NE / 256, 256>>>(dst_idx);
    scan_kernel<<<1, 1024>>>();
    scatter_kernel<<<NE / 256, 256>>>(src_idx, dst_idx);
    s_kernel<<<N_DST / 8, 256>>>(poi_coeff, out_nodes, ncounts);
    aggregate_kernel<<<N_DST, 128>>>(bias_p, out);
}

// round 6
// speedup vs baseline: 2.6075x; 1.3311x over previous
#include <cuda_runtime.h>
#include <cuda_fp16.h>
#include <math.h>
#include <stdint.h>

#define N_SRC   65536
#define N_DST   16384
#define NE      262144
#define IN_F    256
#define HIDD    128
#define NH      4
#define FDIM    512      /* NH*HIDD */
#define KNB     50
#define CAP     1024
#define NEG_SLOPE 0.2f

/* padded row: 72 fp16 = 144 B -> 8 consecutive rows hit 8 distinct 16B
   chunks (mod 128): ldmatrix conflict-free. */
#define ASTRIDE_E 72
#define ASTRIDE_B 144
#define TILE_B    (128 * ASTRIDE_B)     /* 18432 */
#define STAGE_B   (2 * TILE_B)          /* A_hi + B_hi = 36864 */
#define SM_ELS    (2 * STAGE_B)         /* 73728 */
#define SM_ERS    (SM_ELS + 512)
#define SM_TOTAL  (SM_ERS + 512)        /* 74752 -> 2 CTAs/SM */

/* ================= scratch globals ======================================== */
__device__ __half g_feat_h[(size_t)N_SRC * FDIM];   /* 64 MB fp16 */
__device__ __half g_res_h [(size_t)N_DST * FDIM];   /* 16 MB fp16 */
__device__ float  g_dist   [(size_t)N_DST * HIDD];
__device__ float  g_el     [N_SRC * NH];
__device__ float  g_er     [N_DST * NH];
__device__ float  g_s      [N_DST];
__device__ int    g_counts [N_DST];
__device__ int    g_off    [N_DST + 1];
__device__ int    g_cursor [N_DST];
__device__ int    g_csr_src[NE];
__device__ float4 g_csr_e  [NE];
/* pre-converted fp16 images, padded rows */
__device__ __align__(16) __half g_ahi[(size_t)4 * N_SRC * ASTRIDE_E];
__device__ __align__(16) __half g_w1hi[4 * 512 * ASTRIDE_E];
__device__ __align__(16) __half g_w2hi[4 * 512 * ASTRIDE_E];

/* ================= PTX wrappers (arch-generic, sm_80+) ==================== */
__device__ __forceinline__ uint32_t smem_u32(const void* p) {
    uint32_t a;
    asm("{ .reg .u64 t; cvta.to.shared.u64 t, %1; cvt.u32.u64 %0, t; }"
        : "=r"(a) : "l"(p));
    return a;
}
__device__ __forceinline__ void ldsm4(uint32_t* r, uint32_t addr) {
    asm volatile("ldmatrix.sync.aligned.m8n8.x4.shared.b16 {%0,%1,%2,%3}, [%4];"
                 : "=r"(r[0]), "=r"(r[1]), "=r"(r[2]), "=r"(r[3]) : "r"(addr));
}
__device__ __forceinline__ void ldsm2(uint32_t* r, uint32_t addr) {
    asm volatile("ldmatrix.sync.aligned.m8n8.x2.shared.b16 {%0,%1}, [%2];"
                 : "=r"(r[0]), "=r"(r[1]) : "r"(addr));
}
__device__ __forceinline__ void mma16816(float* c, const uint32_t* a, const uint32_t* b) {
    asm volatile("mma.sync.aligned.m16n8k16.row.col.f32.f16.f16.f32 "
                 "{%0,%1,%2,%3}, {%4,%5,%6,%7}, {%8,%9}, {%0,%1,%2,%3};"
                 : "+f"(c[0]), "+f"(c[1]), "+f"(c[2]), "+f"(c[3])
                 : "r"(a[0]), "r"(a[1]), "r"(a[2]), "r"(a[3]),
                   "r"(b[0]), "r"(b[1]));
}
__device__ __forceinline__ void cp16(uint32_t dst, const void* src) {
    asm volatile("cp.async.cg.shared.global [%0], [%1], 16;"
                 :: "r"(dst), "l"(src));
}
#define CP_COMMIT() asm volatile("cp.async.commit_group;" ::: "memory")

/* ================= prep: fp32 -> fp16 padded images ======================= */
__global__ void conv_a_kernel(const float* __restrict__ feat)
{
    int p = blockIdx.x * blockDim.x + threadIdx.x;
    int row = p >> 7;
    int col = (p & 127) * 2;
    int chunk = col >> 6;
    int klocal = col & 63;
    float2 v = *(const float2*)(feat + (size_t)row * IN_F + col);
    size_t off = ((size_t)chunk * N_SRC + row) * ASTRIDE_E + klocal;
    *(__half2*)(g_ahi + off) = __floats2half2_rn(v.x, v.y);
}

__global__ void conv_w_kernel(const float* __restrict__ W, int which)
{
    __half* dhi = which ? g_w2hi : g_w1hi;
    int p = blockIdx.x * blockDim.x + threadIdx.x;
    int n  = p >> 7;
    int col = (p & 127) * 2;
    int chunk = col >> 6;
    int klocal = col & 63;
    float2 v = *(const float2*)(W + (size_t)n * IN_F + col);
    size_t off = (size_t)(chunk * 512 + n) * ASTRIDE_E + klocal;
    *(__half2*)(dhi + off) = __floats2half2_rn(v.x, v.y);
}

/* ================= HMMA GEMM (merged GEMM1+GEMM2) =========================
   out[M,512](fp16) = A[M,256] @ W[512,256]^T, plain fp16.
   grid = (4 heads, 512+128 slabs). y<512 -> GEMM1 (+el/er); else GEMM2.    */
__global__ void __launch_bounds__(256, 2)
tc_gemm(const float* __restrict__ attn_l, const float* __restrict__ attn_r)
{
    extern __shared__ unsigned char smem[];
    const uint32_t sb = smem_u32(smem);
    const int tid  = threadIdx.x;
    const int wid  = tid >> 5;
    const int lane = tid & 31;
    const int wm   = wid & 1;
    const int wn   = wid >> 1;
    const int head = blockIdx.x;
    const int which = (blockIdx.y >= 512);
    const int row0  = (which ? (blockIdx.y - 512) : blockIdx.y) * 128;

    __half* outh = which ? g_res_h : g_feat_h;
    const __half* whi = which ? g_w2hi : g_w1hi;

    float* els = (float*)(smem + SM_ELS);
    float* ers = (float*)(smem + SM_ERS);
    if (which == 0 && tid < 128) { els[tid] = 0.f; ers[tid] = 0.f; }

    float c[4][4][4];
#pragma unroll
    for (int mt = 0; mt < 4; mt++)
#pragma unroll
        for (int nt = 0; nt < 4; nt++)
#pragma unroll
            for (int j = 0; j < 4; j++) c[mt][nt][j] = 0.f;

    const int lr  = tid >> 1;
    const int seg = tid & 1;

    auto load_chunk = [&](int chunk, int stage) {
        const uint32_t st = sb + stage * STAGE_B + (uint32_t)lr * ASTRIDE_B + seg * 64;
        const __half* sa_hi = g_ahi + ((size_t)chunk * N_SRC + row0 + lr) * ASTRIDE_E + seg * 32;
        const __half* sb_hi = whi + (size_t)(chunk * 512 + head * 128 + lr) * ASTRIDE_E + seg * 32;
#pragma unroll
        for (int i = 0; i < 4; i++) {
            cp16(st + i * 16,          sa_hi + i * 8);
            cp16(st + TILE_B + i * 16, sb_hi + i * 8);
        }
    };

    load_chunk(0, 0);
    CP_COMMIT();

    for (int chunk = 0; chunk < 4; chunk++) {
        const int s = chunk & 1;
        if (chunk < 3) {
            load_chunk(chunk + 1, 1 - s);
            CP_COMMIT();
            asm volatile("cp.async.wait_group 1;" ::: "memory");
        } else {
            asm volatile("cp.async.wait_group 0;" ::: "memory");
        }
        __syncthreads();

        const uint32_t a_base = sb + s * STAGE_B
                                + (uint32_t)(wm * 64 + (lane & 15)) * ASTRIDE_B
                                + (uint32_t)(lane >> 4) * 16;
        const uint32_t b_base = sb + s * STAGE_B + TILE_B
                                + (uint32_t)(wn * 32 + (lane & 7)) * ASTRIDE_B
                                + (uint32_t)((lane >> 3) & 1) * 16;
#pragma unroll
        for (int kk = 0; kk < 4; kk++) {
            uint32_t ah[4][4], bh[4][2];
#pragma unroll
            for (int mt = 0; mt < 4; mt++)
                ldsm4(ah[mt], a_base + mt * 16 * ASTRIDE_B + kk * 32);
#pragma unroll
            for (int nt = 0; nt < 4; nt++)
                ldsm2(bh[nt], b_base + nt * 8 * ASTRIDE_B + kk * 32);
#pragma unroll
            for (int mt = 0; mt < 4; mt++)
#pragma unroll
                for (int nt = 0; nt < 4; nt++)
                    mma16816(c[mt][nt], ah[mt], bh[nt]);
        }
        __syncthreads();
    }

    /* ---- epilogue: store C (fp16); fused el/er for which==0 ---- */
    float2 al2[4], ar2[4];
    if (which == 0) {
#pragma unroll
        for (int nt = 0; nt < 4; nt++) {
            int cg = head * 128 + wn * 32 + nt * 8 + (lane & 3) * 2;
            al2[nt] = *(const float2*)(attn_l + cg);
            ar2[nt] = *(const float2*)(attn_r + cg);
        }
    }
#pragma unroll
    for (int mt = 0; mt < 4; mt++) {
        int r0 = wm * 64 + mt * 16 + (lane >> 2);
        int r1 = r0 + 8;
        float pl0 = 0.f, pl1 = 0.f, pr0 = 0.f, pr1 = 0.f;
#pragma unroll
        for (int nt = 0; nt < 4; nt++) {
            int cl = wn * 32 + nt * 8 + (lane & 3) * 2;
            float2 v0 = make_float2(c[mt][nt][0], c[mt][nt][1]);
            float2 v1 = make_float2(c[mt][nt][2], c[mt][nt][3]);
            *(__half2*)(outh + (size_t)(row0 + r0) * FDIM + head * 128 + cl) =
                __floats2half2_rn(v0.x, v0.y);
            *(__half2*)(outh + (size_t)(row0 + r1) * FDIM + head * 128 + cl) =
                __floats2half2_rn(v1.x, v1.y);
            if (which == 0) {
                pl0 = fmaf(v0.x, al2[nt].x, fmaf(v0.y, al2[nt].y, pl0));
                pl1 = fmaf(v1.x, al2[nt].x, fmaf(v1.y, al2[nt].y, pl1));
                pr0 = fmaf(v0.x, ar2[nt].x, fmaf(v0.y, ar2[nt].y, pr0));
                pr1 = fmaf(v1.x, ar2[nt].x, fmaf(v1.y, ar2[nt].y, pr1));
            }
        }
        if (which == 0) {
#pragma unroll
            for (int o = 1; o <= 2; o <<= 1) {
                pl0 += __shfl_xor_sync(0xffffffffu, pl0, o);
                pl1 += __shfl_xor_sync(0xffffffffu, pl1, o);
                pr0 += __shfl_xor_sync(0xffffffffu, pr0, o);
                pr1 += __shfl_xor_sync(0xffffffffu, pr1, o);
            }
            if ((lane & 3) == 0) {
                atomicAdd(&els[r0], pl0); atomicAdd(&els[r1], pl1);
                atomicAdd(&ers[r0], pr0); atomicAdd(&ers[r1], pr1);
            }
        }
    }
    if (which == 0) {
        __syncthreads();
        if (tid < 128) {
            int grow = row0 + tid;
            g_el[grow * NH + head] = els[tid];
            if (grow < N_DST) g_er[grow * NH + head] = ers[tid];
        }
    }
}

/* ================= SIMT GEMM (gathered GEMM3) ============================= */
__global__ void __launch_bounds__(256)
sgemm_nt(const float* __restrict__ A, const float* __restrict__ B,
         const int* __restrict__ gather, int N)
{
    float* Cbase = g_dist;
    __shared__ float As[16][128];
    __shared__ float Bs[16][64];
    const int tid = threadIdx.x;
    const int m0 = blockIdx.x * 128;
    const int n0 = blockIdx.y * 64;
    const int tm = tid >> 4, tn = tid & 15;
    const int ar = tid >> 2, ac = (tid & 3) * 4;

    int grow0 = m0 + ar, grow1 = m0 + ar + 64;
    if (gather) { grow0 = gather[grow0]; grow1 = gather[grow1]; }
    const float* Arow0 = A + (size_t)grow0 * IN_F;
    const float* Arow1 = A + (size_t)grow1 * IN_F;
    const float* Brow  = B + (size_t)(n0 + ar) * IN_F;

    float acc[8][4];
#pragma unroll
    for (int i = 0; i < 8; i++)
#pragma unroll
        for (int j = 0; j < 4; j++) acc[i][j] = 0.f;

    for (int k0 = 0; k0 < IN_F; k0 += 16) {
        float4 va0 = *(const float4*)(Arow0 + k0 + ac);
        float4 va1 = *(const float4*)(Arow1 + k0 + ac);
        float4 vb  = *(const float4*)(Brow  + k0 + ac);
        As[ac + 0][ar]      = va0.x; As[ac + 1][ar]      = va0.y;
        As[ac + 2][ar]      = va0.z; As[ac + 3][ar]      = va0.w;
        As[ac + 0][ar + 64] = va1.x; As[ac + 1][ar + 64] = va1.y;
        As[ac + 2][ar + 64] = va1.z; As[ac + 3][ar + 64] = va1.w;
        Bs[ac + 0][ar] = vb.x; Bs[ac + 1][ar] = vb.y;
        Bs[ac + 2][ar] = vb.z; Bs[ac + 3][ar] = vb.w;
        __syncthreads();
#pragma unroll
        for (int kk = 0; kk < 16; kk++) {
            float4 a0 = *(const float4*)&As[kk][tm * 8];
            float4 a1 = *(const float4*)&As[kk][tm * 8 + 4];
            float4 b  = *(const float4*)&Bs[kk][tn * 4];
            float av[8] = {a0.x, a0.y, a0.z, a0.w, a1.x, a1.y, a1.z, a1.w};
            float bv[4] = {b.x, b.y, b.z, b.w};
#pragma unroll
            for (int i = 0; i < 8; i++)
#pragma unroll
                for (int j = 0; j < 4; j++)
                    acc[i][j] = fmaf(av[i], bv[j], acc[i][j]);
        }
        __syncthreads();
    }
#pragma unroll
    for (int i = 0; i < 8; i++) {
        float4 v = make_float4(acc[i][0], acc[i][1], acc[i][2], acc[i][3]);
        *(float4*)&Cbase[(size_t)(m0 + tm * 8 + i) * N + n0 + tn * 4] = v;
    }
}

/* ================= CSR build ============================================== */
__global__ void zero_counts_kernel() {
    int i = blockIdx.x * blockDim.x + threadIdx.x;
    if (i < N_DST) g_counts[i] = 0;
}

__global__ void hist_kernel(const int* __restrict__ dst_idx)
{
    int e = blockIdx.x * blockDim.x + threadIdx.x;
    if (e < NE) atomicAdd(&g_counts[dst_idx[e]], 1);
}

__global__ void __launch_bounds__(1024) scan_kernel()
{
    __shared__ int tmp[1024];
    const int tid = threadIdx.x;
    const int base = tid * 16;
    int loc[16];
    int s = 0;
#pragma unroll
    for (int j = 0; j < 16; j++) { loc[j] = s; s += g_counts[base + j]; }
    tmp[tid] = s;
    __syncthreads();
    for (int o = 1; o < 1024; o <<= 1) {
        int v = (tid >= o) ? tmp[tid - o] : 0;
        __syncthreads();
        tmp[tid] += v;
        __syncthreads();
    }
    int excl = tmp[tid] - s;
#pragma unroll
    for (int j = 0; j < 16; j++) {
        int v = excl + loc[j];
        g_off[base + j] = v;
        g_cursor[base + j] = v;
    }
    if (tid == 1023) g_off[N_DST] = excl + s;
}

__global__ void scatter_kernel(const int* __restrict__ src_idx,
                               const int* __restrict__ dst_idx)
{
    int e = blockIdx.x * blockDim.x + threadIdx.x;
    if (e >= NE) return;
    int s = src_idx[e];
    int d = dst_idx[e];
    const float* el = g_el + s * NH;
    const float* er = g_er + d * NH;
    float4 ev;
    float x;
    x = el[0] + er[0]; ev.x = (x > 0.f) ? x : NEG_SLOPE * x;
    x = el[1] + er[1]; ev.y = (x > 0.f) ? x : NEG_SLOPE * x;
    x = el[2] + er[2]; ev.z = (x > 0.f) ? x : NEG_SLOPE * x;
    x = el[3] + er[3]; ev.w = (x > 0.f) ? x : NEG_SLOPE * x;
    int pos = atomicAdd(&g_cursor[d], 1);
    g_csr_src[pos] = s;
    g_csr_e[pos]   = ev;
}

__global__ void __launch_bounds__(256)
s_kernel(const float* __restrict__ poi_coeff, const int* __restrict__ output_nodes,
         const int* __restrict__ ncounts)
{
    const int lane = threadIdx.x & 31, warp = threadIdx.x >> 5;
    const int d = blockIdx.x * 8 + warp;
    if (d >= N_DST) return;
    int node = output_nodes[d];
    int c = ncounts[node];
    if (c > KNB) c = KNB;
    float p = 0.f;
    for (int j = lane; j < c; j += 32) p += poi_coeff[(size_t)node * KNB + j];
#pragma unroll
    for (int o = 16; o; o >>= 1) p += __shfl_xor_sync(0xffffffffu, p, o);
    if (lane == 0) g_s[d] = p;
}

/* ================= per-dst softmax + aggregation (fp16 gather) ============ */
__global__ void __launch_bounds__(128)
aggregate_kernel(const float* __restrict__ bias, float* __restrict__ out)
{
    const int d    = blockIdx.x;
    const int tid  = threadIdx.x;
    const int lane = tid & 31, warp = tid >> 5;
    const int beg  = g_off[d];
    const int deg  = g_off[d + 1] - beg;

    __shared__ float sa[CAP * 4];
    __shared__ int   ssrc[CAP];
    __shared__ float red[4][4];
    __shared__ float smx[4], sinv[4];

    /* ---- pass 1: per-head max ---- */
    float m0 = -3e38f, m1 = -3e38f, m2 = -3e38f, m3 = -3e38f;
    for (int e = tid; e < deg; e += 128) {
        float4 v = g_csr_e[beg + e];
        m0 = fmaxf(m0, v.x); m1 = fmaxf(m1, v.y);
        m2 = fmaxf(m2, v.z); m3 = fmaxf(m3, v.w);
    }
#pragma unroll
    for (int o = 16; o; o >>= 1) {
        m0 = fmaxf(m0, __shfl_xor_sync(0xffffffffu, m0, o));
        m1 = fmaxf(m1, __shfl_xor_sync(0xffffffffu, m1, o));
        m2 = fmaxf(m2, __shfl_xor_sync(0xffffffffu, m2, o));
        m3 = fmaxf(m3, __shfl_xor_sync(0xffffffffu, m3, o));
    }
    if (lane == 0) { red[warp][0] = m0; red[warp][1] = m1; red[warp][2] = m2; red[warp][3] = m3; }
    __syncthreads();
    if (tid < 4)
        smx[tid] = fmaxf(fmaxf(red[0][tid], red[1][tid]), fmaxf(red[2][tid], red[3][tid]));
    __syncthreads();
    m0 = smx[0]; m1 = smx[1]; m2 = smx[2]; m3 = smx[3];

    /* ---- pass 2: exp + denom ---- */
    float d0 = 0.f, d1 = 0.f, d2 = 0.f, d3 = 0.f;
    for (int e = tid; e < deg; e += 128) {
        float4 v = g_csr_e[beg + e];
        float w0 = __expf(v.x - m0), w1 = __expf(v.y - m1);
        float w2 = __expf(v.z - m2), w3 = __expf(v.w - m3);
        if (e < CAP) {
            sa[e * 4 + 0] = w0; sa[e * 4 + 1] = w1;
            sa[e * 4 + 2] = w2; sa[e * 4 + 3] = w3;
            ssrc[e] = g_csr_src[beg + e];
        }
        d0 += w0; d1 += w1; d2 += w2; d3 += w3;
    }
#pragma unroll
    for (int o = 16; o; o >>= 1) {
        d0 += __shfl_xor_sync(0xffffffffu, d0, o);
        d1 += __shfl_xor_sync(0xffffffffu, d1, o);
        d2 += __shfl_xor_sync(0xffffffffu, d2, o);
        d3 += __shfl_xor_sync(0xffffffffu, d3, o);
    }
    if (lane == 0) { red[warp][0] = d0; red[warp][1] = d1; red[warp][2] = d2; red[warp][3] = d3; }
    __syncthreads();
    if (tid < 4) {
        float den = red[0][tid] + red[1][tid] + red[2][tid] + red[3][tid];
        sinv[tid] = 1.0f / fmaxf(den, 1e-9f);
    }
    __syncthreads();

    /* ---- pass 3: thread owns 4 dims of one head; 8B fp16 gather/edge ---- */
    const int head = tid >> 5;
    const int q4   = (tid & 31) * 4;
    const int hq   = head * 128 + q4;
    float a0 = 0.f, a1 = 0.f, a2 = 0.f, a3 = 0.f;
    const float mh = (head == 0) ? m0 : (head == 1) ? m1 : (head == 2) ? m2 : m3;
    for (int e = 0; e < deg; e++) {
        int s;
        float w;
        if (e < CAP) {
            s = ssrc[e];
            w = sa[e * 4 + head];
        } else {
            s = g_csr_src[beg + e];
            const float* ep = (const float*)&g_csr_e[beg + e];
            w = __expf(ep[head] - mh);
        }
        uint2 raw = *(const uint2*)(g_feat_h + (size_t)s * FDIM + hq);
        float2 f0 = __half22float2(*(__half2*)&raw.x);
        float2 f1 = __half22float2(*(__half2*)&raw.y);
        a0 = fmaf(w, f0.x, a0);
        a1 = fmaf(w, f0.y, a1);
        a2 = fmaf(w, f1.x, a2);
        a3 = fmaf(w, f1.y, a3);
    }

    /* ---- epilogue: elu(rst + res + bias), +dist*s, /2, relu ---- */
    const float sd = g_s[d];
    const float wi = sinv[head];
    float4 dv = *(const float4*)(g_dist + (size_t)d * HIDD + q4);
    float4 bv = *(const float4*)(bias + hq);
    uint2 rr = *(const uint2*)(g_res_h + (size_t)d * FDIM + hq);
    float2 r0 = __half22float2(*(__half2*)&rr.x);
    float2 r1 = __half22float2(*(__half2*)&rr.y);
    float acc[4] = {a0 * wi, a1 * wi, a2 * wi, a3 * wi};
    float res[4] = {r0.x, r0.y, r1.x, r1.y};
    float dst[4] = {dv.x * sd, dv.y * sd, dv.z * sd, dv.w * sd};
    float bia[4] = {bv.x, bv.y, bv.z, bv.w};
    float4 ov;
    float* po = (float*)&ov;
#pragma unroll
    for (int j = 0; j < 4; j++) {
        float x = acc[j] + res[j] + bia[j];
        float eluv = (x > 0.f) ? x : expm1f(x);
        float o = (eluv + dst[j]) * 0.5f;
        po[j] = (o > 0.f) ? o : 0.f;
    }
    *(float4*)(out + (size_t)d * FDIM + hq) = ov;
}

/* ================= launch ================================================= */
extern "C" void kernel_launch(void* const* d_in, const int* in_sizes, int n_in,
                              void* d_out, int out_size)
{
    const float* feat       = (const float*)d_in[0];
    const float* poi_cat    = (const float*)d_in[1];
    const float* poi_coeff  = (const float*)d_in[2];
    const float* fc_w       = (const float*)d_in[3];
    const float* attn_l     = (const float*)d_in[4];
    const float* attn_r     = (const float*)d_in[5];
    const float* bias_p     = (const float*)d_in[6];
    const float* res_w      = (const float*)d_in[7];
    const float* w_w        = (const float*)d_in[8];
    const int*   src_idx    = (const int*)d_in[9];
    const int*   dst_idx    = (const int*)d_in[10];
    const int*   out_nodes  = (const int*)d_in[11];
    const int*   ncounts    = (const int*)d_in[12];
    float*       out        = (float*)d_out;

    cudaFuncSetAttribute(tc_gemm, cudaFuncAttributeMaxDynamicSharedMemorySize, SM_TOTAL);

    zero_counts_kernel<<<N_DST / 256, 256>>>();
    conv_a_kernel<<<N_SRC * 128 / 256, 256>>>(feat);
    conv_w_kernel<<<256, 256>>>(fc_w, 0);
    conv_w_kernel<<<256, 256>>>(res_w, 1);

    /* merged GEMM1 (+fused el/er) and GEMM2 */
    tc_gemm<<<dim3(4, 512 + 128), 256, SM_TOTAL>>>(attn_l, attn_r);
    /* GEMM3: dist = poi_cat[gather] @ w_w^T */
    sgemm_nt<<<dim3(N_DST / 128, HIDD / 64), 256>>>(poi_cat, w_w, out_nodes, HIDD);

    hist_kernel<<<NE / 256, 256>>>(dst_idx);
    scan_kernel<<<1, 1024>>>();
    scatter_kernel<<<NE / 256, 256>>>(src_idx, dst_idx);
    s_kernel<<<N_DST / 8, 256>>>(poi_coeff, out_nodes, ncounts);
    aggregate_kernel<<<N_DST, 128>>>(bias_p, out);
}

// round 7
// speedup vs baseline: 2.7323x; 1.0479x over previous
#include <cuda_runtime.h>
#include <cuda_fp16.h>
#include <math.h>
#include <stdint.h>

#define N_SRC   65536
#define N_DST   16384
#define NE      262144
#define IN_F    256
#define HIDD    128
#define NH      4
#define FDIM    512      /* NH*HIDD */
#define KNB     50
#define CAP     128
#define NEG_SLOPE 0.2f

/* padded row: 72 fp16 = 144 B -> 8 consecutive rows hit 8 distinct 16B
   chunks (mod 128): ldmatrix conflict-free. */
#define ASTRIDE_E 72
#define ASTRIDE_B 144
#define TILE_B    (128 * ASTRIDE_B)     /* 18432 */
#define STAGE_B   (2 * TILE_B)          /* A_hi + B_hi = 36864 */
#define SM_ELS    (2 * STAGE_B)         /* 73728 */
#define SM_ERS    (SM_ELS + 512)
#define SM_TOTAL  (SM_ERS + 512)        /* 74752 -> 2 CTAs/SM */

/* ================= scratch globals ======================================== */
__device__ __half g_feat_h[(size_t)N_SRC * FDIM];   /* 64 MB fp16 */
__device__ __half g_res_h [(size_t)N_DST * FDIM];   /* 16 MB fp16 */
__device__ __half g_dist_h[(size_t)N_DST * HIDD];   /* 4 MB fp16 */
__device__ float  g_el     [N_SRC * NH];
__device__ float  g_er     [N_DST * NH];
__device__ float  g_s      [N_DST];
__device__ int    g_counts [N_DST];
__device__ int    g_off    [N_DST + 1];
__device__ int    g_cursor [N_DST];
__device__ int    g_csr_src[NE];
__device__ float4 g_csr_e  [NE];
/* pre-converted fp16 images, padded rows */
__device__ __align__(16) __half g_ahi [(size_t)4 * N_SRC * ASTRIDE_E];
__device__ __align__(16) __half g_a3hi[(size_t)4 * N_DST * ASTRIDE_E];
__device__ __align__(16) __half g_w1hi[4 * 512 * ASTRIDE_E];
__device__ __align__(16) __half g_w2hi[4 * 512 * ASTRIDE_E];
__device__ __align__(16) __half g_w3hi[4 * 128 * ASTRIDE_E];

/* ================= PTX wrappers (arch-generic, sm_80+) ==================== */
__device__ __forceinline__ uint32_t smem_u32(const void* p) {
    uint32_t a;
    asm("{ .reg .u64 t; cvta.to.shared.u64 t, %1; cvt.u32.u64 %0, t; }"
        : "=r"(a) : "l"(p));
    return a;
}
__device__ __forceinline__ void ldsm4(uint32_t* r, uint32_t addr) {
    asm volatile("ldmatrix.sync.aligned.m8n8.x4.shared.b16 {%0,%1,%2,%3}, [%4];"
                 : "=r"(r[0]), "=r"(r[1]), "=r"(r[2]), "=r"(r[3]) : "r"(addr));
}
__device__ __forceinline__ void ldsm2(uint32_t* r, uint32_t addr) {
    asm volatile("ldmatrix.sync.aligned.m8n8.x2.shared.b16 {%0,%1}, [%2];"
                 : "=r"(r[0]), "=r"(r[1]) : "r"(addr));
}
__device__ __forceinline__ void mma16816(float* c, const uint32_t* a, const uint32_t* b) {
    asm volatile("mma.sync.aligned.m16n8k16.row.col.f32.f16.f16.f32 "
                 "{%0,%1,%2,%3}, {%4,%5,%6,%7}, {%8,%9}, {%0,%1,%2,%3};"
                 : "+f"(c[0]), "+f"(c[1]), "+f"(c[2]), "+f"(c[3])
                 : "r"(a[0]), "r"(a[1]), "r"(a[2]), "r"(a[3]),
                   "r"(b[0]), "r"(b[1]));
}
__device__ __forceinline__ void cp16(uint32_t dst, const void* src) {
    asm volatile("cp.async.cg.shared.global [%0], [%1], 16;"
                 :: "r"(dst), "l"(src));
}
#define CP_COMMIT() asm volatile("cp.async.commit_group;" ::: "memory")

/* ================= prep: fp32 -> fp16 padded images ======================= */
__global__ void conv_a_kernel(const float* __restrict__ feat)
{
    int p = blockIdx.x * blockDim.x + threadIdx.x;
    int row = p >> 7;
    int col = (p & 127) * 2;
    int chunk = col >> 6;
    int klocal = col & 63;
    float2 v = *(const float2*)(feat + (size_t)row * IN_F + col);
    size_t off = ((size_t)chunk * N_SRC + row) * ASTRIDE_E + klocal;
    *(__half2*)(g_ahi + off) = __floats2half2_rn(v.x, v.y);
}

/* gathered A for GEMM3: poi_cat[out_nodes[row]] */
__global__ void conv_a3_kernel(const float* __restrict__ poi_cat,
                               const int* __restrict__ out_nodes)
{
    int p = blockIdx.x * blockDim.x + threadIdx.x;
    int row = p >> 7;
    int col = (p & 127) * 2;
    int chunk = col >> 6;
    int klocal = col & 63;
    int node = out_nodes[row];
    float2 v = *(const float2*)(poi_cat + (size_t)node * IN_F + col);
    size_t off = ((size_t)chunk * N_DST + row) * ASTRIDE_E + klocal;
    *(__half2*)(g_a3hi + off) = __floats2half2_rn(v.x, v.y);
}

/* which: 0=fc_w(512), 1=res_w(512), 2=w_w(128) */
__global__ void conv_w_kernel(const float* __restrict__ W, int which)
{
    __half* dhi = (which == 0) ? g_w1hi : (which == 1) ? g_w2hi : g_w3hi;
    const int rows = (which == 2) ? 128 : 512;
    int p = blockIdx.x * blockDim.x + threadIdx.x;
    int n  = p >> 7;
    if (n >= rows) return;
    int col = (p & 127) * 2;
    int chunk = col >> 6;
    int klocal = col & 63;
    float2 v = *(const float2*)(W + (size_t)n * IN_F + col);
    size_t off = (size_t)(chunk * rows + n) * ASTRIDE_E + klocal;
    *(__half2*)(dhi + off) = __floats2half2_rn(v.x, v.y);
}

/* ================= HMMA GEMM (merged GEMM1+GEMM2+GEMM3) ===================
   out[M, N](fp16) = A[M,256] @ W[N,256]^T, plain fp16.
   grid = (4 heads, 512+128+128 slabs).
   y<512:   GEMM1 feat->feat_h (+fused el/er)
   y<640:   GEMM2 feat->res_h
   else:    GEMM3 poi_cat[gather]->dist_h (head 0 only, N=128)              */
__global__ void __launch_bounds__(256, 2)
tc_gemm(const float* __restrict__ attn_l, const float* __restrict__ attn_r)
{
    const int head = blockIdx.x;
    const int y    = blockIdx.y;
    const int which = (y >= 512) + (y >= 640);
    if (which == 2 && head != 0) return;   /* uniform exit, before any sync */

    extern __shared__ unsigned char smem[];
    const uint32_t sb = smem_u32(smem);
    const int tid  = threadIdx.x;
    const int wid  = tid >> 5;
    const int lane = tid & 31;
    const int wm   = wid & 1;
    const int wn   = wid >> 1;
    const int row0 = ((which == 0) ? y : (which == 1) ? (y - 512) : (y - 640)) * 128;

    __half* outh = (which == 0) ? g_feat_h : (which == 1) ? g_res_h : g_dist_h;
    const __half* whi = (which == 0) ? g_w1hi : (which == 1) ? g_w2hi : g_w3hi;
    const __half* asrc = (which == 2) ? g_a3hi : g_ahi;
    const int arows  = (which == 2) ? N_DST : N_SRC;
    const int brows  = (which == 2) ? 128 : 512;
    const int ostride = (which == 2) ? HIDD : FDIM;

    float* els = (float*)(smem + SM_ELS);
    float* ers = (float*)(smem + SM_ERS);
    if (which == 0 && tid < 128) { els[tid] = 0.f; ers[tid] = 0.f; }

    float c[4][4][4];
#pragma unroll
    for (int mt = 0; mt < 4; mt++)
#pragma unroll
        for (int nt = 0; nt < 4; nt++)
#pragma unroll
            for (int j = 0; j < 4; j++) c[mt][nt][j] = 0.f;

    const int lr  = tid >> 1;
    const int seg = tid & 1;

    auto load_chunk = [&](int chunk, int stage) {
        const uint32_t st = sb + stage * STAGE_B + (uint32_t)lr * ASTRIDE_B + seg * 64;
        const __half* sa_hi = asrc + ((size_t)chunk * arows + row0 + lr) * ASTRIDE_E + seg * 32;
        const __half* sb_hi = whi + (size_t)(chunk * brows + head * 128 + lr) * ASTRIDE_E + seg * 32;
#pragma unroll
        for (int i = 0; i < 4; i++) {
            cp16(st + i * 16,          sa_hi + i * 8);
            cp16(st + TILE_B + i * 16, sb_hi + i * 8);
        }
    };

    load_chunk(0, 0);
    CP_COMMIT();

    for (int chunk = 0; chunk < 4; chunk++) {
        const int s = chunk & 1;
        if (chunk < 3) {
            load_chunk(chunk + 1, 1 - s);
            CP_COMMIT();
            asm volatile("cp.async.wait_group 1;" ::: "memory");
        } else {
            asm volatile("cp.async.wait_group 0;" ::: "memory");
        }
        __syncthreads();

        const uint32_t a_base = sb + s * STAGE_B
                                + (uint32_t)(wm * 64 + (lane & 15)) * ASTRIDE_B
                                + (uint32_t)(lane >> 4) * 16;
        const uint32_t b_base = sb + s * STAGE_B + TILE_B
                                + (uint32_t)(wn * 32 + (lane & 7)) * ASTRIDE_B
                                + (uint32_t)((lane >> 3) & 1) * 16;
#pragma unroll
        for (int kk = 0; kk < 4; kk++) {
            uint32_t ah[4][4], bh[4][2];
#pragma unroll
            for (int mt = 0; mt < 4; mt++)
                ldsm4(ah[mt], a_base + mt * 16 * ASTRIDE_B + kk * 32);
#pragma unroll
            for (int nt = 0; nt < 4; nt++)
                ldsm2(bh[nt], b_base + nt * 8 * ASTRIDE_B + kk * 32);
#pragma unroll
            for (int mt = 0; mt < 4; mt++)
#pragma unroll
                for (int nt = 0; nt < 4; nt++)
                    mma16816(c[mt][nt], ah[mt], bh[nt]);
        }
        __syncthreads();
    }

    /* ---- epilogue: store C (fp16); fused el/er for which==0 ---- */
    float2 al2[4], ar2[4];
    if (which == 0) {
#pragma unroll
        for (int nt = 0; nt < 4; nt++) {
            int cg = head * 128 + wn * 32 + nt * 8 + (lane & 3) * 2;
            al2[nt] = *(const float2*)(attn_l + cg);
            ar2[nt] = *(const float2*)(attn_r + cg);
        }
    }
#pragma unroll
    for (int mt = 0; mt < 4; mt++) {
        int r0 = wm * 64 + mt * 16 + (lane >> 2);
        int r1 = r0 + 8;
        float pl0 = 0.f, pl1 = 0.f, pr0 = 0.f, pr1 = 0.f;
#pragma unroll
        for (int nt = 0; nt < 4; nt++) {
            int cl = head * 128 + wn * 32 + nt * 8 + (lane & 3) * 2;
            float2 v0 = make_float2(c[mt][nt][0], c[mt][nt][1]);
            float2 v1 = make_float2(c[mt][nt][2], c[mt][nt][3]);
            *(__half2*)(outh + (size_t)(row0 + r0) * ostride + cl) =
                __floats2half2_rn(v0.x, v0.y);
            *(__half2*)(outh + (size_t)(row0 + r1) * ostride + cl) =
                __floats2half2_rn(v1.x, v1.y);
            if (which == 0) {
                pl0 = fmaf(v0.x, al2[nt].x, fmaf(v0.y, al2[nt].y, pl0));
                pl1 = fmaf(v1.x, al2[nt].x, fmaf(v1.y, al2[nt].y, pl1));
                pr0 = fmaf(v0.x, ar2[nt].x, fmaf(v0.y, ar2[nt].y, pr0));
                pr1 = fmaf(v1.x, ar2[nt].x, fmaf(v1.y, ar2[nt].y, pr1));
            }
        }
        if (which == 0) {
#pragma unroll
            for (int o = 1; o <= 2; o <<= 1) {
                pl0 += __shfl_xor_sync(0xffffffffu, pl0, o);
                pl1 += __shfl_xor_sync(0xffffffffu, pl1, o);
                pr0 += __shfl_xor_sync(0xffffffffu, pr0, o);
                pr1 += __shfl_xor_sync(0xffffffffu, pr1, o);
            }
            if ((lane & 3) == 0) {
                atomicAdd(&els[r0], pl0); atomicAdd(&els[r1], pl1);
                atomicAdd(&ers[r0], pr0); atomicAdd(&ers[r1], pr1);
            }
        }
    }
    if (which == 0) {
        __syncthreads();
        if (tid < 128) {
            int grow = row0 + tid;
            g_el[grow * NH + head] = els[tid];
            if (grow < N_DST) g_er[grow * NH + head] = ers[tid];
        }
    }
}

/* ================= CSR build ============================================== */
__global__ void zero_counts_kernel() {
    int i = blockIdx.x * blockDim.x + threadIdx.x;
    if (i < N_DST) g_counts[i] = 0;
}

__global__ void hist_kernel(const int* __restrict__ dst_idx)
{
    int e = blockIdx.x * blockDim.x + threadIdx.x;
    if (e < NE) atomicAdd(&g_counts[dst_idx[e]], 1);
}

__global__ void __launch_bounds__(1024) scan_kernel()
{
    __shared__ int tmp[1024];
    const int tid = threadIdx.x;
    const int base = tid * 16;
    int loc[16];
    int s = 0;
#pragma unroll
    for (int j = 0; j < 16; j++) { loc[j] = s; s += g_counts[base + j]; }
    tmp[tid] = s;
    __syncthreads();
    for (int o = 1; o < 1024; o <<= 1) {
        int v = (tid >= o) ? tmp[tid - o] : 0;
        __syncthreads();
        tmp[tid] += v;
        __syncthreads();
    }
    int excl = tmp[tid] - s;
#pragma unroll
    for (int j = 0; j < 16; j++) {
        int v = excl + loc[j];
        g_off[base + j] = v;
        g_cursor[base + j] = v;
    }
    if (tid == 1023) g_off[N_DST] = excl + s;
}

__global__ void scatter_kernel(const int* __restrict__ src_idx,
                               const int* __restrict__ dst_idx)
{
    int e = blockIdx.x * blockDim.x + threadIdx.x;
    if (e >= NE) return;
    int s = src_idx[e];
    int d = dst_idx[e];
    const float* el = g_el + s * NH;
    const float* er = g_er + d * NH;
    float4 ev;
    float x;
    x = el[0] + er[0]; ev.x = (x > 0.f) ? x : NEG_SLOPE * x;
    x = el[1] + er[1]; ev.y = (x > 0.f) ? x : NEG_SLOPE * x;
    x = el[2] + er[2]; ev.z = (x > 0.f) ? x : NEG_SLOPE * x;
    x = el[3] + er[3]; ev.w = (x > 0.f) ? x : NEG_SLOPE * x;
    int pos = atomicAdd(&g_cursor[d], 1);
    g_csr_src[pos] = s;
    g_csr_e[pos]   = ev;
}

__global__ void __launch_bounds__(256)
s_kernel(const float* __restrict__ poi_coeff, const int* __restrict__ output_nodes,
         const int* __restrict__ ncounts)
{
    const int lane = threadIdx.x & 31, warp = threadIdx.x >> 5;
    const int d = blockIdx.x * 8 + warp;
    if (d >= N_DST) return;
    int node = output_nodes[d];
    int c = ncounts[node];
    if (c > KNB) c = KNB;
    float p = 0.f;
    for (int j = lane; j < c; j += 32) p += poi_coeff[(size_t)node * KNB + j];
#pragma unroll
    for (int o = 16; o; o >>= 1) p += __shfl_xor_sync(0xffffffffu, p, o);
    if (lane == 0) g_s[d] = p;
}

/* ================= per-dst softmax + aggregation (fp16 gather) ============ */
__global__ void __launch_bounds__(128)
aggregate_kernel(const float* __restrict__ bias, float* __restrict__ out)
{
    const int d    = blockIdx.x;
    const int tid  = threadIdx.x;
    const int lane = tid & 31, warp = tid >> 5;
    const int beg  = g_off[d];
    const int deg  = g_off[d + 1] - beg;

    __shared__ float sa[CAP * 4];
    __shared__ int   ssrc[CAP];
    __shared__ float red[4][4];
    __shared__ float smx[4], sinv[4];

    /* ---- pass 1: per-head max ---- */
    float m0 = -3e38f, m1 = -3e38f, m2 = -3e38f, m3 = -3e38f;
    for (int e = tid; e < deg; e += 128) {
        float4 v = g_csr_e[beg + e];
        m0 = fmaxf(m0, v.x); m1 = fmaxf(m1, v.y);
        m2 = fmaxf(m2, v.z); m3 = fmaxf(m3, v.w);
    }
#pragma unroll
    for (int o = 16; o; o >>= 1) {
        m0 = fmaxf(m0, __shfl_xor_sync(0xffffffffu, m0, o));
        m1 = fmaxf(m1, __shfl_xor_sync(0xffffffffu, m1, o));
        m2 = fmaxf(m2, __shfl_xor_sync(0xffffffffu, m2, o));
        m3 = fmaxf(m3, __shfl_xor_sync(0xffffffffu, m3, o));
    }
    if (lane == 0) { red[warp][0] = m0; red[warp][1] = m1; red[warp][2] = m2; red[warp][3] = m3; }
    __syncthreads();
    if (tid < 4)
        smx[tid] = fmaxf(fmaxf(red[0][tid], red[1][tid]), fmaxf(red[2][tid], red[3][tid]));
    __syncthreads();
    m0 = smx[0]; m1 = smx[1]; m2 = smx[2]; m3 = smx[3];

    /* ---- pass 2: exp + denom ---- */
    float d0 = 0.f, d1 = 0.f, d2 = 0.f, d3 = 0.f;
    for (int e = tid; e < deg; e += 128) {
        float4 v = g_csr_e[beg + e];
        float w0 = __expf(v.x - m0), w1 = __expf(v.y - m1);
        float w2 = __expf(v.z - m2), w3 = __expf(v.w - m3);
        if (e < CAP) {
            sa[e * 4 + 0] = w0; sa[e * 4 + 1] = w1;
            sa[e * 4 + 2] = w2; sa[e * 4 + 3] = w3;
            ssrc[e] = g_csr_src[beg + e];
        }
        d0 += w0; d1 += w1; d2 += w2; d3 += w3;
    }
#pragma unroll
    for (int o = 16; o; o >>= 1) {
        d0 += __shfl_xor_sync(0xffffffffu, d0, o);
        d1 += __shfl_xor_sync(0xffffffffu, d1, o);
        d2 += __shfl_xor_sync(0xffffffffu, d2, o);
        d3 += __shfl_xor_sync(0xffffffffu, d3, o);
    }
    if (lane == 0) { red[warp][0] = d0; red[warp][1] = d1; red[warp][2] = d2; red[warp][3] = d3; }
    __syncthreads();
    if (tid < 4) {
        float den = red[0][tid] + red[1][tid] + red[2][tid] + red[3][tid];
        sinv[tid] = 1.0f / fmaxf(den, 1e-9f);
    }
    __syncthreads();

    /* ---- pass 3: thread owns 4 dims of one head; 8B fp16 gather/edge ---- */
    const int head = tid >> 5;
    const int q4   = (tid & 31) * 4;
    const int hq   = head * 128 + q4;
    float a0 = 0.f, a1 = 0.f, a2 = 0.f, a3 = 0.f;
    const float mh = (head == 0) ? m0 : (head == 1) ? m1 : (head == 2) ? m2 : m3;
    for (int e = 0; e < deg; e++) {
        int s;
        float w;
        if (e < CAP) {
            s = ssrc[e];
            w = sa[e * 4 + head];
        } else {
            s = g_csr_src[beg + e];
            const float* ep = (const float*)&g_csr_e[beg + e];
            w = __expf(ep[head] - mh);
        }
        uint2 raw = *(const uint2*)(g_feat_h + (size_t)s * FDIM + hq);
        float2 f0 = __half22float2(*(__half2*)&raw.x);
        float2 f1 = __half22float2(*(__half2*)&raw.y);
        a0 = fmaf(w, f0.x, a0);
        a1 = fmaf(w, f0.y, a1);
        a2 = fmaf(w, f1.x, a2);
        a3 = fmaf(w, f1.y, a3);
    }

    /* ---- epilogue: elu(rst + res + bias), +dist*s, /2, relu ---- */
    const float sd = g_s[d];
    const float wi = sinv[head];
    float4 bv = *(const float4*)(bias + hq);
    uint2 dd = *(const uint2*)(g_dist_h + (size_t)d * HIDD + q4);
    float2 dv0 = __half22float2(*(__half2*)&dd.x);
    float2 dv1 = __half22float2(*(__half2*)&dd.y);
    uint2 rr = *(const uint2*)(g_res_h + (size_t)d * FDIM + hq);
    float2 r0 = __half22float2(*(__half2*)&rr.x);
    float2 r1 = __half22float2(*(__half2*)&rr.y);
    float acc[4] = {a0 * wi, a1 * wi, a2 * wi, a3 * wi};
    float res[4] = {r0.x, r0.y, r1.x, r1.y};
    float dst[4] = {dv0.x * sd, dv0.y * sd, dv1.x * sd, dv1.y * sd};
    float bia[4] = {bv.x, bv.y, bv.z, bv.w};
    float4 ov;
    float* po = (float*)&ov;
#pragma unroll
    for (int j = 0; j < 4; j++) {
        float x = acc[j] + res[j] + bia[j];
        float eluv = (x > 0.f) ? x : expm1f(x);
        float o = (eluv + dst[j]) * 0.5f;
        po[j] = (o > 0.f) ? o : 0.f;
    }
    *(float4*)(out + (size_t)d * FDIM + hq) = ov;
}

/* ================= launch ================================================= */
extern "C" void kernel_launch(void* const* d_in, const int* in_sizes, int n_in,
                              void* d_out, int out_size)
{
    const float* feat       = (const float*)d_in[0];
    const float* poi_cat    = (const float*)d_in[1];
    const float* poi_coeff  = (const float*)d_in[2];
    const float* fc_w       = (const float*)d_in[3];
    const float* attn_l     = (const float*)d_in[4];
    const float* attn_r     = (const float*)d_in[5];
    const float* bias_p     = (const float*)d_in[6];
    const float* res_w      = (const float*)d_in[7];
    const float* w_w        = (const float*)d_in[8];
    const int*   src_idx    = (const int*)d_in[9];
    const int*   dst_idx    = (const int*)d_in[10];
    const int*   out_nodes  = (const int*)d_in[11];
    const int*   ncounts    = (const int*)d_in[12];
    float*       out        = (float*)d_out;

    cudaFuncSetAttribute(tc_gemm, cudaFuncAttributeMaxDynamicSharedMemorySize, SM_TOTAL);

    zero_counts_kernel<<<N_DST / 256, 256>>>();
    conv_a_kernel<<<N_SRC * 128 / 256, 256>>>(feat);
    conv_a3_kernel<<<N_DST * 128 / 256, 256>>>(poi_cat, out_nodes);
    conv_w_kernel<<<256, 256>>>(fc_w, 0);
    conv_w_kernel<<<256, 256>>>(res_w, 1);
    conv_w_kernel<<<64, 256>>>(w_w, 2);

    /* merged GEMM1 (+fused el/er), GEMM2, GEMM3 */
    tc_gemm<<<dim3(4, 512 + 128 + 128), 256, SM_TOTAL>>>(attn_l, attn_r);

    hist_kernel<<<NE / 256, 256>>>(dst_idx);
    scan_kernel<<<1, 1024>>>();
    scatter_kernel<<<NE / 256, 256>>>(src_idx, dst_idx);
    s_kernel<<<N_DST / 8, 256>>>(poi_coeff, out_nodes, ncounts);
    aggregate_kernel<<<N_DST, 128>>>(bias_p, out);
}